// round 15
// baseline (speedup 1.0000x reference)
#include <cuda_runtime.h>
#include <cuda_fp16.h>
#include <math.h>
#include <stdint.h>

#define BSZ 8
#define NB  8
#define MM  512
#define DD  128
#define NN  1024
#define NBK 64
#define NEGV (-1e30f)

#define OFF_YEM 0
#define OFF_DEM 8388608
#define OFF_K   16777216
#define OFF_V   20971520
#define OFF_S   25165824
#define OFF_AGE 25198592

// ---------------- scratch -----------------------------------------------------
__device__ float g_y[NBK * NN * DD];
__device__ uint32_t g_attn16[NBK * NN * (MM / 2)];
__device__ uint32_t g_route16[NBK * NN * (MM / 2)];
__device__ uint32_t g_routeT[NBK * MM * (NN / 2)];
__device__ float g_wnorm[BSZ * NN * DD];
__device__ float g_surp[BSZ * NN];
__device__ float g_novp[NBK * NN];
__device__ float g_rsA[NBK * NN];
__device__ float g_rsR[NBK * NN];
__device__ float g_updK[NBK * MM * DD];
__device__ float g_updV[NBK * MM * DD];
__device__ float g_swr[NBK * MM];
__device__ uint32_t g_Vth[NBK * DD * (MM / 2)];
__device__ uint32_t g_Vtl[NBK * DD * (MM / 2)];
__device__ uint32_t g_WnTh[BSZ * DD * (NN / 2)];
__device__ uint32_t g_WnTl[BSZ * DD * (NN / 2)];
__device__ uint32_t g_WcTh[BSZ * DD * (NN / 2)];
__device__ uint32_t g_WcTl[BSZ * DD * (NN / 2)];
// em_K packed fp16 hi/lo, MMA-tile-contiguous: [bk][kc(8)][m(512)][8 words]
__device__ uint32_t g_KpackH[NBK * 8 * MM * 8];
__device__ uint32_t g_KpackL[NBK * 8 * MM * 8];

// ---------------- helpers -----------------------------------------------------
__device__ __forceinline__ float softplusf(float x) {
    return (x > 20.f) ? x : log1pf(expf(x));
}
__device__ __forceinline__ float sigmoidf(float x) {
    return 1.f / (1.f + __expf(-x));
}
__device__ __forceinline__ uint32_t smem_u32(const void *p) {
    uint32_t a;
    asm("{ .reg .u64 t; cvta.to.shared.u64 t, %1; cvt.u32.u64 %0, t; }"
        : "=r"(a) : "l"(p));
    return a;
}
__device__ __forceinline__ void cp_async16(uint32_t saddr, const void *gaddr) {
    asm volatile("cp.async.cg.shared.global [%0], [%1], 16;"
                 :: "r"(saddr), "l"(gaddr) : "memory");
}
#define CP_COMMIT() asm volatile("cp.async.commit_group;" ::: "memory")
#define CP_WAIT(n)  asm volatile("cp.async.wait_group %0;" :: "n"(n) : "memory")

__device__ __forceinline__ void mma_f16(float d[4], const uint32_t a[4],
                                        uint32_t b0, uint32_t b1) {
    asm volatile(
        "mma.sync.aligned.m16n8k16.row.col.f32.f16.f16.f32 "
        "{%0,%1,%2,%3}, {%4,%5,%6,%7}, {%8,%9}, {%0,%1,%2,%3};"
        : "+f"(d[0]), "+f"(d[1]), "+f"(d[2]), "+f"(d[3])
        : "r"(a[0]), "r"(a[1]), "r"(a[2]), "r"(a[3]), "r"(b0), "r"(b1));
}
__device__ __forceinline__ void split4(float4 x, uint32_t &h01, uint32_t &h23,
                                       uint32_t &l01, uint32_t &l23) {
    __half2 a = __float22half2_rn(make_float2(x.x, x.y));
    __half2 b = __float22half2_rn(make_float2(x.z, x.w));
    float2 fa = __half22float2(a);
    float2 fb = __half22float2(b);
    __half2 la = __float22half2_rn(make_float2(x.x - fa.x, x.y - fa.y));
    __half2 lb = __float22half2_rn(make_float2(x.z - fb.x, x.w - fb.y));
    h01 = *reinterpret_cast<uint32_t *>(&a);
    h23 = *reinterpret_cast<uint32_t *>(&b);
    l01 = *reinterpret_cast<uint32_t *>(&la);
    l23 = *reinterpret_cast<uint32_t *>(&lb);
}
__device__ __forceinline__ void split2(float x, float y, uint32_t &h, uint32_t &l) {
    __half2 a = __float22half2_rn(make_float2(x, y));
    float2 fa = __half22float2(a);
    __half2 la = __float22half2_rn(make_float2(x - fa.x, y - fa.y));
    h = *reinterpret_cast<uint32_t *>(&a);
    l = *reinterpret_cast<uint32_t *>(&la);
}
__device__ __forceinline__ uint32_t pack2(float x, float y) {
    __half2 a = __float22half2_rn(make_float2(x, y));
    return *reinterpret_cast<uint32_t *>(&a);
}

// ---------------- em_K -> packed contiguous chunks ---------------------------------
__global__ void kpack_kernel(const float *__restrict__ emK) {
    int i = blockIdx.x * 256 + threadIdx.x;       // 1,048,576 float4
    int bk = i >> 14;
    int rem = i & 16383;
    int m = rem >> 5, f4 = rem & 31;
    float4 x = reinterpret_cast<const float4 *>(emK)[i];
    uint32_t h01, h23, l01, l23;
    split4(x, h01, h23, l01, l23);
    int kc = f4 >> 2, qw = (f4 & 3) * 2;
    size_t off = ((size_t)(bk * 8 + kc) * 512 + m) * 8 + qw;
    *reinterpret_cast<uint2 *>(&g_KpackH[off]) = make_uint2(h01, h23);
    *reinterpret_cast<uint2 *>(&g_KpackL[off]) = make_uint2(l01, l23);
}

// ---------------- V transpose + pack ---------------------------------------------
__global__ void transpose_v_kernel(const float *__restrict__ emV) {
    __shared__ float t[32][33];
    int bk = blockIdx.z;
    int m0 = blockIdx.x * 32, d0 = blockIdx.y * 32;
    int x = threadIdx.x, y0 = threadIdx.y;
#pragma unroll
    for (int yy = 0; yy < 32; yy += 8)
        t[y0 + yy][x] = emV[((size_t)bk * MM + m0 + y0 + yy) * DD + d0 + x];
    __syncthreads();
    int px = x & 15, hl = x >> 4;
#pragma unroll
    for (int yy = 0; yy < 32; yy += 8) {
        int dl = y0 + yy;
        float v0 = t[2 * px][dl], v1 = t[2 * px + 1][dl];
        uint32_t h, l;
        split2(v0, v1, h, l);
        size_t idx = ((size_t)bk * DD + d0 + dl) * (MM / 2) + m0 / 2 + px;
        if (hl == 0) g_Vth[idx] = h;
        else         g_Vtl[idx] = l;
    }
}

// ---------------- wnorm/wcand transpose + pack --------------------------------------
__global__ void wtpack_kernel(const float *__restrict__ wcand) {
    __shared__ float t1[32][33], t2[32][33];
    int b = blockIdx.z;
    int n0 = blockIdx.x * 32, d0 = blockIdx.y * 32;
    int x = threadIdx.x, y0 = threadIdx.y;
#pragma unroll
    for (int yy = 0; yy < 32; yy += 8) {
        size_t src = ((size_t)b * NN + n0 + y0 + yy) * DD + d0 + x;
        t1[y0 + yy][x] = g_wnorm[src];
        t2[y0 + yy][x] = wcand[src];
    }
    __syncthreads();
    int px = x & 15, hl = x >> 4;
#pragma unroll
    for (int yy = 0; yy < 32; yy += 8) {
        int dl = y0 + yy;
        size_t idx = ((size_t)b * DD + d0 + dl) * (NN / 2) + n0 / 2 + px;
        uint32_t h, l;
        split2(t1[2 * px][dl], t1[2 * px + 1][dl], h, l);
        if (hl == 0) g_WnTh[idx] = h; else g_WnTl[idx] = l;
        split2(t2[2 * px][dl], t2[2 * px + 1][dl], h, l);
        if (hl == 0) g_WcTh[idx] = h; else g_WcTl[idx] = l;
    }
}

// ---------------- y init ----------------------------------------------------------
__global__ void init_y_kernel(const float *__restrict__ seed) {
    int i = blockIdx.x * 256 + threadIdx.x;
    int bk = i >> 15;
    int rem = i & 32767;
    int b = bk >> 3;
    reinterpret_cast<float4 *>(g_y)[i] =
        reinterpret_cast<const float4 *>(seed)[b * 32768 + rem];
}

// ---------------- w_norm + surprise magnitude -------------------------------------
__global__ void wnorm_kernel(const float *__restrict__ wc,
                             const float *__restrict__ sp) {
    int row = blockIdx.x;
    int tid = threadIdx.x;
    float w = wc[row * DD + tid];
    float s = sp[row * DD + tid];
    float a = w * w, bb = s * s;
#pragma unroll
    for (int o = 16; o; o >>= 1) {
        a  += __shfl_xor_sync(0xffffffffu, a, o);
        bb += __shfl_xor_sync(0xffffffffu, bb, o);
    }
    __shared__ float ra[4], rb[4];
    if ((tid & 31) == 0) { ra[tid >> 5] = a; rb[tid >> 5] = bb; }
    __syncthreads();
    float na = ra[0] + ra[1] + ra[2] + ra[3];
    float nb = rb[0] + rb[1] + rb[2] + rb[3];
    g_wnorm[row * DD + tid] = w / fmaxf(sqrtf(na), 1e-12f);
    if (tid == 0) g_surp[row] = sqrtf(nb);
}

// ---------------- scores: packed K (3-stage ring), Y pre-split up-front -------------
// block 64n x 512m, 512 thr, 16 warps (wr 2 x wc 8); 8 kc of 16 d. word offsets:
// K stages: st*12288 (KH), st*12288+6144 (KL), 3 stages = 36864
#define S3_YH    36864
#define S3_YL    43008
#define S3_RED   49152
#define S3_SSV   49664
#define S3_YRAW  24576
#define S3_WORDS 50176
#define S3_BYTES (S3_WORDS * 4)

template <int MODE>
__global__ __launch_bounds__(512) void scores_mma_kernel(
    const float *__restrict__ emS,
    const float *__restrict__ rtau, const float *__restrict__ rtauw) {
    extern __shared__ __align__(16) float sm[];
    uint32_t *smU = reinterpret_cast<uint32_t *>(sm);
    float *RED = sm + S3_RED;
    float *SSV = sm + S3_SSV;
    uint32_t sb = smem_u32(sm);

    int bk = blockIdx.y, b = bk >> 3, k = bk & 7;
    int n0 = blockIdx.x * 64;
    int tid = threadIdx.x, w = tid >> 5, lane = tid & 31;
    int wr = w >> 3, wc = w & 7;
    int g = lane >> 2, tig = lane & 3;

    const float *Yb = (MODE == 0) ? (g_y + (size_t)bk * NN * DD)
                                  : (g_wnorm + (size_t)b * NN * DD);
    const uint32_t *KHg = g_KpackH + (size_t)bk * 8 * 512 * 8;
    const uint32_t *KLg = g_KpackL + (size_t)bk * 8 * 512 * 8;

    float d[2][8][4];
#pragma unroll
    for (int nt = 0; nt < 2; nt++)
#pragma unroll
        for (int mt = 0; mt < 8; mt++)
#pragma unroll
            for (int c = 0; c < 4; c++) d[nt][mt][c] = 0.f;

    auto prefetch = [&](int kc, int st) {
#pragma unroll
        for (int i = 0; i < 2; i++) {
            int f = tid + i * 512;
            int m = f >> 1, q = f & 1;
            size_t src = ((size_t)kc * 512 + m) * 8 + q * 4;
            cp_async16(sb + (st * 12288 + m * 12 + q * 4) * 4, KHg + src);
            cp_async16(sb + (st * 12288 + 6144 + m * 12 + q * 4) * 4, KLg + src);
        }
        CP_COMMIT();
    };

    // K stages 0,1 + raw Y up-front
    prefetch(0, 0);
    prefetch(1, 1);
#pragma unroll
    for (int i = 0; i < 4; i++) {   // Y raw: 64 rows x 128 floats
        int f = tid + i * 512;
        int row = f >> 5, q = f & 31;
        cp_async16(sb + (S3_YRAW + row * 128 + q * 4) * 4,
                   Yb + (size_t)(n0 + row) * DD + q * 4);
    }
    CP_COMMIT();
    CP_WAIT(0);
    __syncthreads();
    // split Y once: [kc][row][12]
#pragma unroll
    for (int i = 0; i < 4; i++) {
        int f = tid + i * 512;
        int row = f >> 5, q = f & 31;
        float4 x = *reinterpret_cast<const float4 *>(&sm[S3_YRAW + row * 128 + q * 4]);
        uint32_t h01, h23, l01, l23;
        split4(x, h01, h23, l01, l23);
        int kc = q >> 2, qw = (q & 3) * 2;
        *reinterpret_cast<uint2 *>(&smU[S3_YH + kc * 768 + row * 12 + qw]) =
            make_uint2(h01, h23);
        *reinterpret_cast<uint2 *>(&smU[S3_YL + kc * 768 + row * 12 + qw]) =
            make_uint2(l01, l23);
    }
    __syncthreads();

    for (int kc = 0; kc < 8; kc++) {
        int st = kc % 3;
        if (kc == 7) { CP_WAIT(0); } else { CP_WAIT(1); }
        __syncthreads();            // stage kc%3 ready; prior MMAs done
        if (kc + 2 < 8) prefetch(kc + 2, (kc + 2) % 3);
        uint32_t ah[2][4], al[2][4];
        int yh = S3_YH + kc * 768, yl = S3_YL + kc * 768;
#pragma unroll
        for (int nt = 0; nt < 2; nt++) {
            int r0 = wr * 32 + nt * 16 + g;
            ah[nt][0] = smU[yh + r0 * 12 + tig];
            ah[nt][1] = smU[yh + (r0 + 8) * 12 + tig];
            ah[nt][2] = smU[yh + r0 * 12 + tig + 4];
            ah[nt][3] = smU[yh + (r0 + 8) * 12 + tig + 4];
            al[nt][0] = smU[yl + r0 * 12 + tig];
            al[nt][1] = smU[yl + (r0 + 8) * 12 + tig];
            al[nt][2] = smU[yl + r0 * 12 + tig + 4];
            al[nt][3] = smU[yl + (r0 + 8) * 12 + tig + 4];
        }
        int kh = st * 12288, kl = st * 12288 + 6144;
#pragma unroll
        for (int mt = 0; mt < 8; mt++) {
            int m = wc * 64 + mt * 8 + g;
            uint32_t bh0 = smU[kh + m * 12 + tig];
            uint32_t bh1 = smU[kh + m * 12 + tig + 4];
            uint32_t bl0 = smU[kl + m * 12 + tig];
            uint32_t bl1 = smU[kl + m * 12 + tig + 4];
#pragma unroll
            for (int nt = 0; nt < 2; nt++) {
                mma_f16(d[nt][mt], ah[nt], bh0, bh1);
                mma_f16(d[nt][mt], ah[nt], bl0, bl1);
                mma_f16(d[nt][mt], al[nt], bh0, bh1);
            }
        }
    }
    __syncthreads();

    // ---- epilogue (R13/R14 proven) ----------------------------------------------
    float sv = emS[bk * MM + tid];
    SSV[tid] = sv;
    int hasAny = __syncthreads_or(sv > 0.f);

    bool act[8][2];
#pragma unroll
    for (int mt = 0; mt < 8; mt++) {
        int c = wc * 64 + mt * 8 + tig * 2;
        act[mt][0] = SSV[c] > 0.f;
        act[mt][1] = SSV[c + 1] > 0.f;
    }
    float inv_tau  = 1.f / (softplusf(rtau[k]) + 0.1f);
    float inv_tauw = 1.f / (softplusf(rtauw[k]) + 0.1f);

#pragma unroll
    for (int nt = 0; nt < 2; nt++) {
        float m0 = NEGV, m1 = NEGV;
#pragma unroll
        for (int mt = 0; mt < 8; mt++) {
            if (act[mt][0]) { m0 = fmaxf(m0, d[nt][mt][0]); m1 = fmaxf(m1, d[nt][mt][2]); }
            if (act[mt][1]) { m0 = fmaxf(m0, d[nt][mt][1]); m1 = fmaxf(m1, d[nt][mt][3]); }
        }
#pragma unroll
        for (int o = 1; o <= 2; o <<= 1) {
            m0 = fmaxf(m0, __shfl_xor_sync(0xffffffffu, m0, o));
            m1 = fmaxf(m1, __shfl_xor_sync(0xffffffffu, m1, o));
        }
        if (tig == 0) {
            RED[(wr * 32 + nt * 16 + g) * 8 + wc] = m0;
            RED[(wr * 32 + nt * 16 + g + 8) * 8 + wc] = m1;
        }
    }
    __syncthreads();
    float gmx[2][2];
#pragma unroll
    for (int nt = 0; nt < 2; nt++)
#pragma unroll
        for (int h = 0; h < 2; h++) {
            int r = wr * 32 + nt * 16 + g + h * 8;
            float m = RED[r * 8];
#pragma unroll
            for (int i = 1; i < 8; i++) m = fmaxf(m, RED[r * 8 + i]);
            gmx[nt][h] = m;
        }
    __syncthreads();

    int np = (MODE == 1) ? 2 : 1;
    for (int p = 0; p < np; p++) {
        float sc = (p == 0) ? inv_tau : inv_tauw;
        uint32_t *op = (p == 0) ? g_attn16 : g_route16;
        float rs[2][2] = {{0.f, 0.f}, {0.f, 0.f}};
#pragma unroll
        for (int nt = 0; nt < 2; nt++) {
            int rlo = n0 + wr * 32 + nt * 16 + g;
#pragma unroll
            for (int mt = 0; mt < 8; mt++) {
                float e00, e01, e10, e11;
                if (!hasAny) { e00 = e01 = e10 = e11 = 1.f; }
                else {
                    e00 = act[mt][0] ? __expf((d[nt][mt][0] - gmx[nt][0]) * sc) : 0.f;
                    e01 = act[mt][1] ? __expf((d[nt][mt][1] - gmx[nt][0]) * sc) : 0.f;
                    e10 = act[mt][0] ? __expf((d[nt][mt][2] - gmx[nt][1]) * sc) : 0.f;
                    e11 = act[mt][1] ? __expf((d[nt][mt][3] - gmx[nt][1]) * sc) : 0.f;
                }
                rs[nt][0] += e00 + e01;
                rs[nt][1] += e10 + e11;
                size_t w0 = ((size_t)bk * NN + rlo) * 256 + wc * 32 + mt * 4 + tig;
                op[w0] = pack2(e00, e01);
                op[w0 + 8 * 256] = pack2(e10, e11);
            }
#pragma unroll
            for (int o = 1; o <= 2; o <<= 1) {
                rs[nt][0] += __shfl_xor_sync(0xffffffffu, rs[nt][0], o);
                rs[nt][1] += __shfl_xor_sync(0xffffffffu, rs[nt][1], o);
            }
            if (tig == 0) {
                RED[(wr * 32 + nt * 16 + g) * 8 + wc] = rs[nt][0];
                RED[(wr * 32 + nt * 16 + g + 8) * 8 + wc] = rs[nt][1];
            }
        }
        __syncthreads();
        if (tid < 64) {
            float t = 0.f;
#pragma unroll
            for (int i = 0; i < 8; i++) t += RED[tid * 8 + i];
            size_t nidx = (size_t)bk * NN + n0 + tid;
            if (p == 0) g_rsA[nidx] = hasAny ? (1.f / t) : 0.f;
            else        g_rsR[nidx] = 1.f / t;
        }
        __syncthreads();
    }
}

// ---------------- A@V: 32-m chunks (16 iters), 3-stage ring, stride-20 rows ----------
// stage (words, rel st*7680): AH 0, VH 2560, VL 5120.
#define A3_PSQ 23040
#define A3_NV 23296
#define A3_WORDS 23424
#define A3_BYTES (A3_WORDS * 4)

template <int MODE>
__global__ __launch_bounds__(256, 2) void av_mma_kernel(
    const float *__restrict__ w1, const float *__restrict__ w2,
    const float *__restrict__ gb, const float *__restrict__ seed,
    const float *__restrict__ wcand, float *__restrict__ out) {
    extern __shared__ __align__(16) float sm[];
    uint32_t *smU = reinterpret_cast<uint32_t *>(sm);
    float *PSQ = sm + A3_PSQ;
    float *NV  = sm + A3_NV;
    uint32_t sb = smem_u32(sm);

    int bk = blockIdx.y, b = bk >> 3, kd = bk & 7;
    int n0 = blockIdx.x * 128;
    int tid = threadIdx.x, w = tid >> 5, lane = tid & 31;
    int nr = w & 3, dc = w >> 2;
    int g = lane >> 2, tig = lane & 3;

    const uint32_t *AHb = g_attn16 + (size_t)bk * NN * 256;
    const uint32_t *VHb = g_Vth + (size_t)bk * DD * 256;
    const uint32_t *VLb = g_Vtl + (size_t)bk * DD * 256;

    float d[2][8][4];
#pragma unroll
    for (int nt = 0; nt < 2; nt++)
#pragma unroll
        for (int mt = 0; mt < 8; mt++)
#pragma unroll
            for (int c = 0; c < 4; c++) d[nt][mt][c] = 0.f;

    auto prefetch = [&](int mc, int st) {
        int base = st * 7680;
#pragma unroll
        for (int i = 0; i < 2; i++) {
            int f = tid + i * 256;
            int row = f >> 2, q = f & 3;
            uint32_t dst = (row * 20 + q * 4) * 4;
            cp_async16(sb + base * 4 + dst,
                       AHb + (size_t)(n0 + row) * 256 + mc * 16 + q * 4);
            cp_async16(sb + (base + 2560) * 4 + dst,
                       VHb + (size_t)row * 256 + mc * 16 + q * 4);
            cp_async16(sb + (base + 5120) * 4 + dst,
                       VLb + (size_t)row * 256 + mc * 16 + q * 4);
        }
        CP_COMMIT();
    };

    prefetch(0, 0);
    prefetch(1, 1);
    for (int mc = 0; mc < 16; mc++) {
        int st = mc % 3;
        if (mc == 15) { CP_WAIT(0); } else { CP_WAIT(1); }
        __syncthreads();
        if (mc + 2 < 16) prefetch(mc + 2, (mc + 2) % 3);
        int base = st * 7680;
        int ahO = base, vhO = base + 2560, vlO = base + 5120;
#pragma unroll
        for (int ks = 0; ks < 2; ks++) {
            int k0 = ks * 8;
            uint32_t ah[2][4];
#pragma unroll
            for (int nt = 0; nt < 2; nt++) {
                int r0 = nr * 32 + nt * 16 + g;
                ah[nt][0] = smU[ahO + r0 * 20 + k0 + tig];
                ah[nt][1] = smU[ahO + (r0 + 8) * 20 + k0 + tig];
                ah[nt][2] = smU[ahO + r0 * 20 + k0 + tig + 4];
                ah[nt][3] = smU[ahO + (r0 + 8) * 20 + k0 + tig + 4];
            }
#pragma unroll
            for (int mt = 0; mt < 8; mt++) {
                int dr = dc * 64 + mt * 8 + g;
                uint32_t bh0 = smU[vhO + dr * 20 + k0 + tig];
                uint32_t bh1 = smU[vhO + dr * 20 + k0 + tig + 4];
                uint32_t bl0 = smU[vlO + dr * 20 + k0 + tig];
                uint32_t bl1 = smU[vlO + dr * 20 + k0 + tig + 4];
#pragma unroll
                for (int nt = 0; nt < 2; nt++) {
                    mma_f16(d[nt][mt], ah[nt], bh0, bh1);
                    mma_f16(d[nt][mt], ah[nt], bl0, bl1);
                }
            }
        }
    }
    __syncthreads();

    if (MODE == 0 || MODE == 1) {
        float2 w1c[8], w2c[8], gbc[8];
#pragma unroll
        for (int mt = 0; mt < 8; mt++) {
            int d2 = dc * 64 + mt * 8 + tig * 2;
            w1c[mt] = *reinterpret_cast<const float2 *>(&w1[kd * DD + d2]);
            w2c[mt] = *reinterpret_cast<const float2 *>(&w2[kd * DD + d2]);
            gbc[mt] = *reinterpret_cast<const float2 *>(&gb[kd * DD + d2]);
        }
#pragma unroll
        for (int nt = 0; nt < 2; nt++)
#pragma unroll
            for (int hf = 0; hf < 2; hf++) {
                int row = nr * 32 + nt * 16 + g + hf * 8;
                int n = n0 + row;
                float s = g_rsA[(size_t)bk * NN + n];
                size_t yb = ((size_t)bk * NN + n) * DD;
#pragma unroll
                for (int mt = 0; mt < 8; mt++) {
                    int d2 = dc * 64 + mt * 8 + tig * 2;
                    float2 yo = *reinterpret_cast<const float2 *>(&g_y[yb + d2]);
                    float dl0 = s * d[nt][mt][hf * 2];
                    float dl1 = s * d[nt][mt][hf * 2 + 1];
                    float g0 = sigmoidf(w1c[mt].x * yo.x + w2c[mt].x * dl0 + gbc[mt].x);
                    float g1 = sigmoidf(w1c[mt].y * yo.y + w2c[mt].y * dl1 + gbc[mt].y);
                    float2 yn = make_float2(yo.x + g0 * dl0, yo.y + g1 * dl1);
                    if (MODE == 0) {
                        *reinterpret_cast<float2 *>(&g_y[yb + d2]) = yn;
                    } else {
                        float2 sd = *reinterpret_cast<const float2 *>(
                            &seed[((size_t)b * NN + n) * DD + d2]);
                        *reinterpret_cast<float2 *>(
                            &out[OFF_YEM + (((size_t)b * NN + n) * NB + kd) * DD + d2]) =
                            make_float2(yn.x - sd.x, yn.y - sd.y);
                    }
                }
            }
    } else {
#pragma unroll
        for (int nt = 0; nt < 2; nt++)
#pragma unroll
            for (int hf = 0; hf < 2; hf++) {
                int row = nr * 32 + nt * 16 + g + hf * 8;
                int n = n0 + row;
                float s = g_rsA[(size_t)bk * NN + n];
                size_t wb = ((size_t)b * NN + n) * DD;
                float p = 0.f;
#pragma unroll
                for (int mt = 0; mt < 8; mt++) {
                    int d2 = dc * 64 + mt * 8 + tig * 2;
                    float2 wv = *reinterpret_cast<const float2 *>(&wcand[wb + d2]);
                    float r0 = wv.x - s * d[nt][mt][hf * 2];
                    float r1 = wv.y - s * d[nt][mt][hf * 2 + 1];
                    p += r0 * r0 + r1 * r1;
                }
                p += __shfl_xor_sync(0xffffffffu, p, 1);
                p += __shfl_xor_sync(0xffffffffu, p, 2);
                if (tig == 0) PSQ[row * 2 + dc] = p;
            }
        __syncthreads();
        if (tid < 128) {
            int n = n0 + tid;
            float nv = 0.5f * g_surp[b * NN + n] +
                       0.5f * sqrtf(PSQ[tid * 2] + PSQ[tid * 2 + 1]);
            NV[tid] = nv;
            g_novp[(size_t)bk * NN + n] = nv * g_rsR[(size_t)bk * NN + n];
        }
        __syncthreads();
#pragma unroll
        for (int nt = 0; nt < 2; nt++)
#pragma unroll
            for (int hf = 0; hf < 2; hf++) {
                int row = nr * 32 + nt * 16 + g + hf * 8;
                int n = n0 + row;
                float nv = NV[row];
                size_t wb = ((size_t)b * NN + n) * DD;
                size_t ob = OFF_DEM + (((size_t)b * NN + n) * NB + kd) * DD;
#pragma unroll
                for (int mt = 0; mt < 8; mt++) {
                    int d2 = dc * 64 + mt * 8 + tig * 2;
                    float2 wv = *reinterpret_cast<const float2 *>(&wcand[wb + d2]);
                    *reinterpret_cast<float2 *>(&out[ob + d2]) =
                        make_float2(nv * wv.x, nv * wv.y);
                }
            }
    }
}

// ---------------- repack (R14-proven) ------------------------------------------------
__global__ __launch_bounds__(256) void repack_kernel() {
    __shared__ uint32_t t[64][68];
    __shared__ float nov[64];
    int bk = blockIdx.y, mt4 = blockIdx.x;
    int tid = threadIdx.x;
    int mp = tid >> 2, jq = tid & 3;
    int m0 = mt4 * 128, mp0 = mt4 * 64;
    size_t rbase = (size_t)bk * MM * (NN / 2);
    float s0 = 0.f, s1 = 0.f;

    for (int nc = 0; nc < 16; nc++) {
        int n0 = nc * 64;
#pragma unroll
        for (int i = 0; i < 4; i++) {
            int f = tid + i * 256;
            int row = f >> 4, q = f & 15;
            *reinterpret_cast<uint4 *>(&t[row][q * 4]) =
                *reinterpret_cast<const uint4 *>(
                    &g_route16[((size_t)bk * NN + n0 + row) * 256 + mp0 + q * 4]);
        }
        if (tid < 64) nov[tid] = g_novp[(size_t)bk * NN + n0 + tid];
        __syncthreads();
#pragma unroll
        for (int i = 0; i < 8; i++) {
            int j = jq + i * 4;
            __half2 h0 = *reinterpret_cast<__half2 *>(&t[2 * j][mp]);
            __half2 h1 = *reinterpret_cast<__half2 *>(&t[2 * j + 1][mp]);
            __half2 lo = __lows2half2(h0, h1);
            __half2 hi = __highs2half2(h0, h1);
            float nv0 = nov[2 * j], nv1 = nov[2 * j + 1];
            __half2 nv2 = __floats2half2_rn(nv0, nv1);
            __half2 olo = __hmul2(lo, nv2);
            __half2 ohi = __hmul2(hi, nv2);
            size_t jg = n0 / 2 + j;
            g_routeT[rbase + (size_t)(m0 + 2 * mp) * 512 + jg] =
                *reinterpret_cast<uint32_t *>(&olo);
            g_routeT[rbase + (size_t)(m0 + 2 * mp + 1) * 512 + jg] =
                *reinterpret_cast<uint32_t *>(&ohi);
            float2 flo = __half22float2(lo), fhi = __half22float2(hi);
            s0 += nv0 * flo.x + nv1 * flo.y;
            s1 += nv0 * fhi.x + nv1 * fhi.y;
        }
        __syncthreads();
    }
    s0 += __shfl_xor_sync(0xffffffffu, s0, 1);
    s0 += __shfl_xor_sync(0xffffffffu, s0, 2);
    s1 += __shfl_xor_sync(0xffffffffu, s1, 1);
    s1 += __shfl_xor_sync(0xffffffffu, s1, 2);
    if (jq == 0) {
        g_swr[bk * MM + m0 + 2 * mp] = s0;
        g_swr[bk * MM + m0 + 2 * mp + 1] = s1;
    }
}

// ---------------- update_K/V: pure fp16 packed GEMM (R14-proven) ---------------------
#define U2_NH   1280
#define U2_NL   3840
#define U2_CH   6400
#define U2_CL   8960
#define U2_STAGE 11520
#define U2_BYTES (2 * U2_STAGE * 4)

__global__ __launch_bounds__(256, 2) void updkv_mma_kernel() {
    extern __shared__ __align__(16) float sm[];
    uint32_t *smU = reinterpret_cast<uint32_t *>(sm);
    uint32_t sb = smem_u32(sm);

    int bk = blockIdx.y, b = bk >> 3;
    int m0 = blockIdx.x * 64;
    int tid = threadIdx.x, w = tid >> 5, lane = tid & 31;
    int mr = w & 3, dc = w >> 2;
    int g = lane >> 2, tig = lane & 3;

    const uint32_t *RTg = g_routeT + (size_t)bk * MM * 512;
    const uint32_t *NHg = g_WnTh + (size_t)b * DD * 512;
    const uint32_t *NLg = g_WnTl + (size_t)b * DD * 512;
    const uint32_t *CHg = g_WcTh + (size_t)b * DD * 512;
    const uint32_t *CLg = g_WcTl + (size_t)b * DD * 512;

    float dK[8][4], dV[8][4];
#pragma unroll
    for (int mt = 0; mt < 8; mt++)
#pragma unroll
        for (int c = 0; c < 4; c++) { dK[mt][c] = 0.f; dV[mt][c] = 0.f; }

    auto prefetch = [&](int nc, int st) {
        int base = st * U2_STAGE;
        {
            int row = tid >> 2, q = tid & 3;
            cp_async16(sb + (base + row * 20 + q * 4) * 4,
                       RTg + (size_t)(m0 + row) * 512 + nc * 16 + q * 4);
        }
#pragma unroll
        for (int i = 0; i < 2; i++) {
            int f = tid + i * 256;
            int row = f >> 2, q = f & 3;
            size_t src = (size_t)row * 512 + nc * 16 + q * 4;
            uint32_t dst = (row * 20 + q * 4) * 4;
            cp_async16(sb + (base + U2_NH) * 4 + dst, NHg + src);
            cp_async16(sb + (base + U2_NL) * 4 + dst, NLg + src);
            cp_async16(sb + (base + U2_CH) * 4 + dst, CHg + src);
            cp_async16(sb + (base + U2_CL) * 4 + dst, CLg + src);
        }
        CP_COMMIT();
    };

    prefetch(0, 0);
    for (int nc = 0; nc < 32; nc++) {
        int st = nc & 1;
        if (nc < 31) { prefetch(nc + 1, st ^ 1); CP_WAIT(1); }
        else         { CP_WAIT(0); }
        __syncthreads();
        int base = st * U2_STAGE;
        const uint32_t *RT = smU + base;
        const uint32_t *NH = smU + base + U2_NH;
        const uint32_t *NL = smU + base + U2_NL;
        const uint32_t *CH = smU + base + U2_CH;
        const uint32_t *CL = smU + base + U2_CL;
#pragma unroll
        for (int ks = 0; ks < 2; ks++) {
            int k0 = ks * 8;
            int ar = mr * 16 + g;
            uint32_t A[4];
            A[0] = RT[ar * 20 + k0 + tig];
            A[1] = RT[(ar + 8) * 20 + k0 + tig];
            A[2] = RT[ar * 20 + k0 + tig + 4];
            A[3] = RT[(ar + 8) * 20 + k0 + tig + 4];
#pragma unroll
            for (int mt = 0; mt < 8; mt++) {
                int dcol = dc * 64 + mt * 8 + g;
                uint32_t nh0 = NH[dcol * 20 + k0 + tig];
                uint32_t nh1 = NH[dcol * 20 + k0 + tig + 4];
                uint32_t nl0 = NL[dcol * 20 + k0 + tig];
                uint32_t nl1 = NL[dcol * 20 + k0 + tig + 4];
                uint32_t ch0 = CH[dcol * 20 + k0 + tig];
                uint32_t ch1 = CH[dcol * 20 + k0 + tig + 4];
                uint32_t cl0 = CL[dcol * 20 + k0 + tig];
                uint32_t cl1 = CL[dcol * 20 + k0 + tig + 4];
                mma_f16(dK[mt], A, nh0, nh1);
                mma_f16(dK[mt], A, nl0, nl1);
                mma_f16(dV[mt], A, ch0, ch1);
                mma_f16(dV[mt], A, cl0, cl1);
            }
        }
        __syncthreads();
    }

#pragma unroll
    for (int mt = 0; mt < 8; mt++) {
        int m_row = m0 + mr * 16 + g;
        int d2 = dc * 64 + mt * 8 + tig * 2;
        size_t o0 = ((size_t)bk * MM + m_row) * DD + d2;
        size_t o1 = ((size_t)bk * MM + m_row + 8) * DD + d2;
        *reinterpret_cast<float2 *>(&g_updK[o0]) = make_float2(dK[mt][0], dK[mt][1]);
        *reinterpret_cast<float2 *>(&g_updK[o1]) = make_float2(dK[mt][2], dK[mt][3]);
        *reinterpret_cast<float2 *>(&g_updV[o0]) = make_float2(dV[mt][0], dV[mt][1]);
        *reinterpret_cast<float2 *>(&g_updV[o1]) = make_float2(dV[mt][2], dV[mt][3]);
    }
}

// ---------------- final ---------------------------------------------------------------
__global__ __launch_bounds__(256) void final_kernel(
    const float *__restrict__ emK, const float *__restrict__ emV,
    const float *__restrict__ emS, const float *__restrict__ emAge,
    const float *__restrict__ gem, float *__restrict__ out) {
    int bk = blockIdx.x, b = bk >> 3, k = bk & 7;
    int tid = threadIdx.x, warp = tid >> 5, lane = tid & 31;
    float ge = gem[b * NB + k];
    const float invN = 1.f / (float)NN;

    for (int m = warp; m < MM; m += 8) {
        float swv = g_swr[bk * MM + m];
        float denom = fmaxf(swv, 1e-8f);
        float alpha = fminf(ge * swv * invN, 1.f);
        float oma = 1.f - alpha;
        float idn = 1.f / denom;
        size_t off = ((size_t)bk * MM + m) * DD + lane * 4;
        float4 uk = *reinterpret_cast<const float4 *>(&g_updK[off]);
        uk.x *= idn; uk.y *= idn; uk.z *= idn; uk.w *= idn;
        float sq = uk.x * uk.x + uk.y * uk.y + uk.z * uk.z + uk.w * uk.w;
#pragma unroll
        for (int o = 16; o; o >>= 1) sq += __shfl_xor_sync(0xffffffffu, sq, o);
        float inv = 1.f / fmaxf(sqrtf(sq), 1e-12f);
        float ai = alpha * inv;
        float4 ek = *reinterpret_cast<const float4 *>(&emK[off]);
        *reinterpret_cast<float4 *>(&out[OFF_K + off]) =
            make_float4(oma * ek.x + ai * uk.x, oma * ek.y + ai * uk.y,
                        oma * ek.z + ai * uk.z, oma * ek.w + ai * uk.w);
        float4 uv = *reinterpret_cast<const float4 *>(&g_updV[off]);
        uv.x *= idn; uv.y *= idn; uv.z *= idn; uv.w *= idn;
        float4 ev = *reinterpret_cast<const float4 *>(&emV[off]);
        *reinterpret_cast<float4 *>(&out[OFF_V + off]) =
            make_float4(oma * ev.x + alpha * uv.x, oma * ev.y + alpha * uv.y,
                        oma * ev.z + alpha * uv.z, oma * ev.w + alpha * uv.w);
    }

    __shared__ float red[8];
    __shared__ float stot;
    float part = 0.f, sn[2], al[2];
#pragma unroll
    for (int i = 0; i < 2; i++) {
        int m = tid + i * 256;
        float swv = g_swr[bk * MM + m];
        al[i] = fminf(ge * swv * invN, 1.f);
        float v = emS[bk * MM + m] + al[i];
        v = fminf(fmaxf(v, 0.f), 3.0f);
        sn[i] = v; part += v;
    }
#pragma unroll
    for (int o = 16; o; o >>= 1) part += __shfl_xor_sync(0xffffffffu, part, o);
    if (lane == 0) red[warp] = part;
    __syncthreads();
    if (tid == 0) {
        float t = 0.f;
        for (int i = 0; i < 8; i++) t += red[i];
        stot = t;
    }
    __syncthreads();
    float scale = fminf(1.f, 32.0f / fmaxf(stot, 1e-8f));
#pragma unroll
    for (int i = 0; i < 2; i++) {
        int m = tid + i * 256;
        out[OFF_S + bk * MM + m] = sn[i] * scale;
        out[OFF_AGE + bk * MM + m] = emAge[bk * MM + m] * (1.f - al[i]);
    }
}

// ---------------- launcher --------------------------------------------------------------
extern "C" void kernel_launch(void *const *d_in, const int *in_sizes, int n_in,
                              void *d_out, int out_size) {
    const float *seed     = (const float *)d_in[0];
    const float *wcand    = (const float *)d_in[1];
    const float *surprise = (const float *)d_in[2];
    const float *gem      = (const float *)d_in[3];
    const float *emK      = (const float *)d_in[4];
    const float *emV      = (const float *)d_in[5];
    const float *emS      = (const float *)d_in[6];
    const float *emAge    = (const float *)d_in[7];
    const float *w1       = (const float *)d_in[8];
    const float *w2       = (const float *)d_in[9];
    const float *gb       = (const float *)d_in[10];
    const float *rtau     = (const float *)d_in[11];
    const float *rtauw    = (const float *)d_in[12];
    float *out = (float *)d_out;

    cudaFuncSetAttribute(scores_mma_kernel<0>,
                         cudaFuncAttributeMaxDynamicSharedMemorySize, S3_BYTES);
    cudaFuncSetAttribute(scores_mma_kernel<1>,
                         cudaFuncAttributeMaxDynamicSharedMemorySize, S3_BYTES);
    cudaFuncSetAttribute(av_mma_kernel<0>,
                         cudaFuncAttributeMaxDynamicSharedMemorySize, A3_BYTES);
    cudaFuncSetAttribute(av_mma_kernel<1>,
                         cudaFuncAttributeMaxDynamicSharedMemorySize, A3_BYTES);
    cudaFuncSetAttribute(av_mma_kernel<2>,
                         cudaFuncAttributeMaxDynamicSharedMemorySize, A3_BYTES);
    cudaFuncSetAttribute(updkv_mma_kernel,
                         cudaFuncAttributeMaxDynamicSharedMemorySize, U2_BYTES);

    dim3 gS(16, 64), gA(8, 64), gU(8, 64);
    dim3 gT(16, 4, 64), bT(32, 8);
    dim3 gW(32, 4, 8);

    kpack_kernel<<<4096, 256>>>(emK);
    transpose_v_kernel<<<gT, bT>>>(emV);
    init_y_kernel<<<8192, 256>>>(seed);
    wnorm_kernel<<<8192, 128>>>(wcand, surprise);
    wtpack_kernel<<<gW, bT>>>(wcand);

    scores_mma_kernel<0><<<gS, 512, S3_BYTES>>>(emS, rtau, rtauw);
    av_mma_kernel<0><<<gA, 256, A3_BYTES>>>(w1, w2, gb, seed, wcand, out);
    scores_mma_kernel<0><<<gS, 512, S3_BYTES>>>(emS, rtau, rtauw);
    av_mma_kernel<1><<<gA, 256, A3_BYTES>>>(w1, w2, gb, seed, wcand, out);

    scores_mma_kernel<1><<<gS, 512, S3_BYTES>>>(emS, rtau, rtauw);
    av_mma_kernel<2><<<gA, 256, A3_BYTES>>>(w1, w2, gb, seed, wcand, out);

    repack_kernel<<<dim3(4, 64), 256>>>();
    updkv_mma_kernel<<<gU, 256, U2_BYTES>>>();
    final_kernel<<<64, 256>>>(emK, emV, emS, emAge, gem, out);
}

// round 16
// speedup vs baseline: 1.1733x; 1.1733x over previous
#include <cuda_runtime.h>
#include <cuda_fp16.h>
#include <math.h>
#include <stdint.h>

#define BSZ 8
#define NB  8
#define MM  512
#define DD  128
#define NN  1024
#define NBK 64
#define NEGV (-1e30f)

#define OFF_YEM 0
#define OFF_DEM 8388608
#define OFF_K   16777216
#define OFF_V   20971520
#define OFF_S   25165824
#define OFF_AGE 25198592

// ---------------- scratch -----------------------------------------------------
__device__ float g_y[NBK * NN * DD];
__device__ uint32_t g_attn16[NBK * NN * (MM / 2)];
__device__ uint32_t g_route16[NBK * NN * (MM / 2)];
__device__ uint32_t g_routeT[NBK * MM * (NN / 2)];
__device__ float g_wnorm[BSZ * NN * DD];
__device__ float g_surp[BSZ * NN];
__device__ float g_novp[NBK * NN];
__device__ float g_rsA[NBK * NN];
__device__ float g_rsR[NBK * NN];
__device__ float g_updK[NBK * MM * DD];
__device__ float g_updV[NBK * MM * DD];
__device__ float g_swr[NBK * MM];
__device__ uint32_t g_Vth[NBK * DD * (MM / 2)];
__device__ uint32_t g_Vtl[NBK * DD * (MM / 2)];
__device__ uint32_t g_WnTh[BSZ * DD * (NN / 2)];
__device__ uint32_t g_WnTl[BSZ * DD * (NN / 2)];
__device__ uint32_t g_WcTh[BSZ * DD * (NN / 2)];
__device__ uint32_t g_WcTl[BSZ * DD * (NN / 2)];
// em_K packed fp16 hi/lo, swizzled stride-8 rows: [bk][kc(8)][m(512)][8 words]
__device__ uint32_t g_KpackH[NBK * 8 * MM * 8];
__device__ uint32_t g_KpackL[NBK * 8 * MM * 8];

// ---------------- helpers -----------------------------------------------------
__device__ __forceinline__ float softplusf(float x) {
    return (x > 20.f) ? x : log1pf(expf(x));
}
__device__ __forceinline__ float sigmoidf(float x) {
    return 1.f / (1.f + __expf(-x));
}
__device__ __forceinline__ uint32_t smem_u32(const void *p) {
    uint32_t a;
    asm("{ .reg .u64 t; cvta.to.shared.u64 t, %1; cvt.u32.u64 %0, t; }"
        : "=r"(a) : "l"(p));
    return a;
}
__device__ __forceinline__ void cp_async16(uint32_t saddr, const void *gaddr) {
    asm volatile("cp.async.cg.shared.global [%0], [%1], 16;"
                 :: "r"(saddr), "l"(gaddr) : "memory");
}
#define CP_COMMIT() asm volatile("cp.async.commit_group;" ::: "memory")
#define CP_WAIT(n)  asm volatile("cp.async.wait_group %0;" :: "n"(n) : "memory")

__device__ __forceinline__ void mma_f16(float d[4], const uint32_t a[4],
                                        uint32_t b0, uint32_t b1) {
    asm volatile(
        "mma.sync.aligned.m16n8k16.row.col.f32.f16.f16.f32 "
        "{%0,%1,%2,%3}, {%4,%5,%6,%7}, {%8,%9}, {%0,%1,%2,%3};"
        : "+f"(d[0]), "+f"(d[1]), "+f"(d[2]), "+f"(d[3])
        : "r"(a[0]), "r"(a[1]), "r"(a[2]), "r"(a[3]), "r"(b0), "r"(b1));
}
__device__ __forceinline__ void split4(float4 x, uint32_t &h01, uint32_t &h23,
                                       uint32_t &l01, uint32_t &l23) {
    __half2 a = __float22half2_rn(make_float2(x.x, x.y));
    __half2 b = __float22half2_rn(make_float2(x.z, x.w));
    float2 fa = __half22float2(a);
    float2 fb = __half22float2(b);
    __half2 la = __float22half2_rn(make_float2(x.x - fa.x, x.y - fa.y));
    __half2 lb = __float22half2_rn(make_float2(x.z - fb.x, x.w - fb.y));
    h01 = *reinterpret_cast<uint32_t *>(&a);
    h23 = *reinterpret_cast<uint32_t *>(&b);
    l01 = *reinterpret_cast<uint32_t *>(&la);
    l23 = *reinterpret_cast<uint32_t *>(&lb);
}
__device__ __forceinline__ void split2(float x, float y, uint32_t &h, uint32_t &l) {
    __half2 a = __float22half2_rn(make_float2(x, y));
    float2 fa = __half22float2(a);
    __half2 la = __float22half2_rn(make_float2(x - fa.x, y - fa.y));
    h = *reinterpret_cast<uint32_t *>(&a);
    l = *reinterpret_cast<uint32_t *>(&la);
}
__device__ __forceinline__ uint32_t pack2(float x, float y) {
    __half2 a = __float22half2_rn(make_float2(x, y));
    return *reinterpret_cast<uint32_t *>(&a);
}

// ---------------- em_K -> packed swizzled chunks -----------------------------------
__global__ void kpack_kernel(const float *__restrict__ emK) {
    int i = blockIdx.x * 256 + threadIdx.x;       // 1,048,576 float4
    int bk = i >> 14;
    int rem = i & 16383;
    int m = rem >> 5, f4 = rem & 31;
    float4 x = reinterpret_cast<const float4 *>(emK)[i];
    uint32_t h01, h23, l01, l23;
    split4(x, h01, h23, l01, l23);
    int kc = f4 >> 2, qw = (f4 & 3) * 2;
    int qwp = qw ^ (((m >> 2) & 1) << 2);         // swizzle group by (m>>2)&1
    size_t off = ((size_t)(bk * 8 + kc) * 512 + m) * 8 + qwp;
    *reinterpret_cast<uint2 *>(&g_KpackH[off]) = make_uint2(h01, h23);
    *reinterpret_cast<uint2 *>(&g_KpackL[off]) = make_uint2(l01, l23);
}

// ---------------- V transpose + pack ---------------------------------------------
__global__ void transpose_v_kernel(const float *__restrict__ emV) {
    __shared__ float t[32][33];
    int bk = blockIdx.z;
    int m0 = blockIdx.x * 32, d0 = blockIdx.y * 32;
    int x = threadIdx.x, y0 = threadIdx.y;
#pragma unroll
    for (int yy = 0; yy < 32; yy += 8)
        t[y0 + yy][x] = emV[((size_t)bk * MM + m0 + y0 + yy) * DD + d0 + x];
    __syncthreads();
    int px = x & 15, hl = x >> 4;
#pragma unroll
    for (int yy = 0; yy < 32; yy += 8) {
        int dl = y0 + yy;
        float v0 = t[2 * px][dl], v1 = t[2 * px + 1][dl];
        uint32_t h, l;
        split2(v0, v1, h, l);
        size_t idx = ((size_t)bk * DD + d0 + dl) * (MM / 2) + m0 / 2 + px;
        if (hl == 0) g_Vth[idx] = h;
        else         g_Vtl[idx] = l;
    }
}

// ---------------- wnorm/wcand transpose + pack --------------------------------------
__global__ void wtpack_kernel(const float *__restrict__ wcand) {
    __shared__ float t1[32][33], t2[32][33];
    int b = blockIdx.z;
    int n0 = blockIdx.x * 32, d0 = blockIdx.y * 32;
    int x = threadIdx.x, y0 = threadIdx.y;
#pragma unroll
    for (int yy = 0; yy < 32; yy += 8) {
        size_t src = ((size_t)b * NN + n0 + y0 + yy) * DD + d0 + x;
        t1[y0 + yy][x] = g_wnorm[src];
        t2[y0 + yy][x] = wcand[src];
    }
    __syncthreads();
    int px = x & 15, hl = x >> 4;
#pragma unroll
    for (int yy = 0; yy < 32; yy += 8) {
        int dl = y0 + yy;
        size_t idx = ((size_t)b * DD + d0 + dl) * (NN / 2) + n0 / 2 + px;
        uint32_t h, l;
        split2(t1[2 * px][dl], t1[2 * px + 1][dl], h, l);
        if (hl == 0) g_WnTh[idx] = h; else g_WnTl[idx] = l;
        split2(t2[2 * px][dl], t2[2 * px + 1][dl], h, l);
        if (hl == 0) g_WcTh[idx] = h; else g_WcTl[idx] = l;
    }
}

// ---------------- y init ----------------------------------------------------------
__global__ void init_y_kernel(const float *__restrict__ seed) {
    int i = blockIdx.x * 256 + threadIdx.x;
    int bk = i >> 15;
    int rem = i & 32767;
    int b = bk >> 3;
    reinterpret_cast<float4 *>(g_y)[i] =
        reinterpret_cast<const float4 *>(seed)[b * 32768 + rem];
}

// ---------------- w_norm + surprise magnitude -------------------------------------
__global__ void wnorm_kernel(const float *__restrict__ wc,
                             const float *__restrict__ sp) {
    int row = blockIdx.x;
    int tid = threadIdx.x;
    float w = wc[row * DD + tid];
    float s = sp[row * DD + tid];
    float a = w * w, bb = s * s;
#pragma unroll
    for (int o = 16; o; o >>= 1) {
        a  += __shfl_xor_sync(0xffffffffu, a, o);
        bb += __shfl_xor_sync(0xffffffffu, bb, o);
    }
    __shared__ float ra[4], rb[4];
    if ((tid & 31) == 0) { ra[tid >> 5] = a; rb[tid >> 5] = bb; }
    __syncthreads();
    float na = ra[0] + ra[1] + ra[2] + ra[3];
    float nb = rb[0] + rb[1] + rb[2] + rb[3];
    g_wnorm[row * DD + tid] = w / fmaxf(sqrtf(na), 1e-12f);
    if (tid == 0) g_surp[row] = sqrtf(nb);
}

// ---------------- scores v4: 256 thr, 32n x 512m, 2 blocks/SM -----------------------
// 8 warps, each 32n x 64m (wc = warp). K: 2-stage swizzled packed; Y: up-front split.
// smem words: K stages 2x8192=16384; YH 16384(+3072); YL 19456(+3072);
// RED 22528(256); SSV 22784(512) -> 23296 words
#define S4_YH    16384
#define S4_YL    19456
#define S4_RED   22528
#define S4_SSV   22784
#define S4_WORDS 23296
#define S4_BYTES (S4_WORDS * 4)

template <int MODE>
__global__ __launch_bounds__(256, 2) void scores_mma_kernel(
    const float *__restrict__ emS,
    const float *__restrict__ rtau, const float *__restrict__ rtauw) {
    extern __shared__ __align__(16) float sm[];
    uint32_t *smU = reinterpret_cast<uint32_t *>(sm);
    float *RED = sm + S4_RED;
    float *SSV = sm + S4_SSV;
    uint32_t sb = smem_u32(sm);

    int bk = blockIdx.y, b = bk >> 3, k = bk & 7;
    int n0 = blockIdx.x * 32;
    int tid = threadIdx.x, wc = tid >> 5, lane = tid & 31;
    int g = lane >> 2, tig = lane & 3;
    int sm4 = ((g >> 2) & 1) * 4;          // swizzle group select for K rows

    const float *Yb = (MODE == 0) ? (g_y + (size_t)bk * NN * DD)
                                  : (g_wnorm + (size_t)b * NN * DD);
    const uint32_t *KHg = g_KpackH + (size_t)bk * 8 * 512 * 8;
    const uint32_t *KLg = g_KpackL + (size_t)bk * 8 * 512 * 8;

    float d[2][8][4];
#pragma unroll
    for (int nt = 0; nt < 2; nt++)
#pragma unroll
        for (int mt = 0; mt < 8; mt++)
#pragma unroll
            for (int c = 0; c < 4; c++) d[nt][mt][c] = 0.f;

    auto prefetch = [&](int kc, int st) {   // pure linear copy, 32KB
#pragma unroll
        for (int i = 0; i < 4; i++) {
            int f = tid + i * 256;          // f4 index 0..1023
            cp_async16(sb + (st * 8192 + f * 4) * 4,
                       KHg + (size_t)kc * 4096 + f * 4);
            cp_async16(sb + (st * 8192 + 4096 + f * 4) * 4,
                       KLg + (size_t)kc * 4096 + f * 4);
        }
        CP_COMMIT();
    };

    prefetch(0, 0);
    // Y: 32 rows x 128 d, LDG + split up-front
#pragma unroll
    for (int i = 0; i < 4; i++) {
        int f = tid + i * 256;
        int row = f >> 5, q = f & 31;
        float4 x = *reinterpret_cast<const float4 *>(
            &Yb[(size_t)(n0 + row) * DD + q * 4]);
        uint32_t h01, h23, l01, l23;
        split4(x, h01, h23, l01, l23);
        int kc = q >> 2, qw = (q & 3) * 2;
        *reinterpret_cast<uint2 *>(&smU[S4_YH + kc * 384 + row * 12 + qw]) =
            make_uint2(h01, h23);
        *reinterpret_cast<uint2 *>(&smU[S4_YL + kc * 384 + row * 12 + qw]) =
            make_uint2(l01, l23);
    }

    for (int kc = 0; kc < 8; kc++) {
        int st = kc & 1;
        CP_WAIT(0);
        __syncthreads();                    // stage st + (kc==0: Y) visible
        if (kc + 1 < 8) prefetch(kc + 1, st ^ 1);
        uint32_t ah[2][4], al[2][4];
        int yh = S4_YH + kc * 384, yl = S4_YL + kc * 384;
#pragma unroll
        for (int nt = 0; nt < 2; nt++) {
            int r0 = nt * 16 + g;
            ah[nt][0] = smU[yh + r0 * 12 + tig];
            ah[nt][1] = smU[yh + (r0 + 8) * 12 + tig];
            ah[nt][2] = smU[yh + r0 * 12 + tig + 4];
            ah[nt][3] = smU[yh + (r0 + 8) * 12 + tig + 4];
            al[nt][0] = smU[yl + r0 * 12 + tig];
            al[nt][1] = smU[yl + (r0 + 8) * 12 + tig];
            al[nt][2] = smU[yl + r0 * 12 + tig + 4];
            al[nt][3] = smU[yl + (r0 + 8) * 12 + tig + 4];
        }
        int kh = st * 8192, kl = st * 8192 + 4096;
#pragma unroll
        for (int mt = 0; mt < 8; mt++) {
            int m = wc * 64 + mt * 8 + g;
            uint32_t bh0 = smU[kh + m * 8 + sm4 + tig];
            uint32_t bh1 = smU[kh + m * 8 + (4 - sm4) + tig];
            uint32_t bl0 = smU[kl + m * 8 + sm4 + tig];
            uint32_t bl1 = smU[kl + m * 8 + (4 - sm4) + tig];
#pragma unroll
            for (int nt = 0; nt < 2; nt++) {
                mma_f16(d[nt][mt], ah[nt], bh0, bh1);
                mma_f16(d[nt][mt], ah[nt], bl0, bl1);
                mma_f16(d[nt][mt], al[nt], bh0, bh1);
            }
        }
    }
    __syncthreads();

    // ---- epilogue (R14 structure, 32 rows / 8 warps) -------------------------------
    float sv0 = emS[bk * MM + tid];
    float sv1 = emS[bk * MM + 256 + tid];
    SSV[tid] = sv0;
    SSV[256 + tid] = sv1;
    int hasAny = __syncthreads_or(sv0 > 0.f || sv1 > 0.f);

    bool act[8][2];
#pragma unroll
    for (int mt = 0; mt < 8; mt++) {
        int c = wc * 64 + mt * 8 + tig * 2;
        act[mt][0] = SSV[c] > 0.f;
        act[mt][1] = SSV[c + 1] > 0.f;
    }
    float inv_tau  = 1.f / (softplusf(rtau[k]) + 0.1f);
    float inv_tauw = 1.f / (softplusf(rtauw[k]) + 0.1f);

#pragma unroll
    for (int nt = 0; nt < 2; nt++) {
        float m0 = NEGV, m1 = NEGV;
#pragma unroll
        for (int mt = 0; mt < 8; mt++) {
            if (act[mt][0]) { m0 = fmaxf(m0, d[nt][mt][0]); m1 = fmaxf(m1, d[nt][mt][2]); }
            if (act[mt][1]) { m0 = fmaxf(m0, d[nt][mt][1]); m1 = fmaxf(m1, d[nt][mt][3]); }
        }
#pragma unroll
        for (int o = 1; o <= 2; o <<= 1) {
            m0 = fmaxf(m0, __shfl_xor_sync(0xffffffffu, m0, o));
            m1 = fmaxf(m1, __shfl_xor_sync(0xffffffffu, m1, o));
        }
        if (tig == 0) {
            RED[(nt * 16 + g) * 8 + wc] = m0;
            RED[(nt * 16 + g + 8) * 8 + wc] = m1;
        }
    }
    __syncthreads();
    float gmx[2][2];
#pragma unroll
    for (int nt = 0; nt < 2; nt++)
#pragma unroll
        for (int h = 0; h < 2; h++) {
            int r = nt * 16 + g + h * 8;
            float m = RED[r * 8];
#pragma unroll
            for (int i = 1; i < 8; i++) m = fmaxf(m, RED[r * 8 + i]);
            gmx[nt][h] = m;
        }
    __syncthreads();

    int np = (MODE == 1) ? 2 : 1;
    for (int p = 0; p < np; p++) {
        float sc = (p == 0) ? inv_tau : inv_tauw;
        uint32_t *op = (p == 0) ? g_attn16 : g_route16;
        float rs[2][2] = {{0.f, 0.f}, {0.f, 0.f}};
#pragma unroll
        for (int nt = 0; nt < 2; nt++) {
            int rlo = n0 + nt * 16 + g;
#pragma unroll
            for (int mt = 0; mt < 8; mt++) {
                float e00, e01, e10, e11;
                if (!hasAny) { e00 = e01 = e10 = e11 = 1.f; }
                else {
                    e00 = act[mt][0] ? __expf((d[nt][mt][0] - gmx[nt][0]) * sc) : 0.f;
                    e01 = act[mt][1] ? __expf((d[nt][mt][1] - gmx[nt][0]) * sc) : 0.f;
                    e10 = act[mt][0] ? __expf((d[nt][mt][2] - gmx[nt][1]) * sc) : 0.f;
                    e11 = act[mt][1] ? __expf((d[nt][mt][3] - gmx[nt][1]) * sc) : 0.f;
                }
                rs[nt][0] += e00 + e01;
                rs[nt][1] += e10 + e11;
                size_t w0 = ((size_t)bk * NN + rlo) * 256 + wc * 32 + mt * 4 + tig;
                op[w0] = pack2(e00, e01);
                op[w0 + 8 * 256] = pack2(e10, e11);
            }
#pragma unroll
            for (int o = 1; o <= 2; o <<= 1) {
                rs[nt][0] += __shfl_xor_sync(0xffffffffu, rs[nt][0], o);
                rs[nt][1] += __shfl_xor_sync(0xffffffffu, rs[nt][1], o);
            }
            if (tig == 0) {
                RED[(nt * 16 + g) * 8 + wc] = rs[nt][0];
                RED[(nt * 16 + g + 8) * 8 + wc] = rs[nt][1];
            }
        }
        __syncthreads();
        if (tid < 32) {
            float t = 0.f;
#pragma unroll
            for (int i = 0; i < 8; i++) t += RED[tid * 8 + i];
            size_t nidx = (size_t)bk * NN + n0 + tid;
            if (p == 0) g_rsA[nidx] = hasAny ? (1.f / t) : 0.f;
            else        g_rsR[nidx] = 1.f / t;
        }
        __syncthreads();
    }
}

// ---------------- A@V (R14-proven): attn fp16-hi x (Vhi+Vlo), 3-stage ring ----------
#define AV_PSQ 13824
#define AV_NV 14080
#define AV_WORDS 14208
#define AV_BYTES (AV_WORDS * 4)

template <int MODE>
__global__ __launch_bounds__(256, 2) void av_mma_kernel(
    const float *__restrict__ w1, const float *__restrict__ w2,
    const float *__restrict__ gb, const float *__restrict__ seed,
    const float *__restrict__ wcand, float *__restrict__ out) {
    extern __shared__ __align__(16) float sm[];
    uint32_t *smU = reinterpret_cast<uint32_t *>(sm);
    float *PSQ = sm + AV_PSQ;
    float *NV  = sm + AV_NV;
    uint32_t sb = smem_u32(sm);

    int bk = blockIdx.y, b = bk >> 3, kd = bk & 7;
    int n0 = blockIdx.x * 128;
    int tid = threadIdx.x, w = tid >> 5, lane = tid & 31;
    int nr = w & 3, dc = w >> 2;
    int g = lane >> 2, tig = lane & 3;

    const uint32_t *AHb = g_attn16 + (size_t)bk * NN * 256;
    const uint32_t *VHb = g_Vth + (size_t)bk * DD * 256;
    const uint32_t *VLb = g_Vtl + (size_t)bk * DD * 256;

    float d[2][8][4];
#pragma unroll
    for (int nt = 0; nt < 2; nt++)
#pragma unroll
        for (int mt = 0; mt < 8; mt++)
#pragma unroll
            for (int c = 0; c < 4; c++) d[nt][mt][c] = 0.f;

    auto prefetch = [&](int mc, int st) {
        int row = tid >> 1, q = tid & 1;
        int base = st * 4608;
        cp_async16(sb + (base + row * 12 + q * 4) * 4,
                   AHb + (size_t)(n0 + row) * 256 + mc * 8 + q * 4);
        cp_async16(sb + (base + 1536 + row * 12 + q * 4) * 4,
                   VHb + (size_t)row * 256 + mc * 8 + q * 4);
        cp_async16(sb + (base + 3072 + row * 12 + q * 4) * 4,
                   VLb + (size_t)row * 256 + mc * 8 + q * 4);
        CP_COMMIT();
    };

    prefetch(0, 0);
    prefetch(1, 1);
    for (int mc = 0; mc < 32; mc++) {
        int st = mc % 3;
        if (mc == 31) { CP_WAIT(0); } else { CP_WAIT(1); }
        __syncthreads();
        if (mc + 2 < 32) prefetch(mc + 2, (mc + 2) % 3);
        int base = st * 4608;
        int ahO = base, vhO = base + 1536, vlO = base + 3072;
        uint32_t ah[2][4];
#pragma unroll
        for (int nt = 0; nt < 2; nt++) {
            int r0 = nr * 32 + nt * 16 + g;
            ah[nt][0] = smU[ahO + r0 * 12 + tig];
            ah[nt][1] = smU[ahO + (r0 + 8) * 12 + tig];
            ah[nt][2] = smU[ahO + r0 * 12 + tig + 4];
            ah[nt][3] = smU[ahO + (r0 + 8) * 12 + tig + 4];
        }
#pragma unroll
        for (int mt = 0; mt < 8; mt++) {
            int dr = dc * 64 + mt * 8 + g;
            uint32_t bh0 = smU[vhO + dr * 12 + tig];
            uint32_t bh1 = smU[vhO + dr * 12 + tig + 4];
            uint32_t bl0 = smU[vlO + dr * 12 + tig];
            uint32_t bl1 = smU[vlO + dr * 12 + tig + 4];
#pragma unroll
            for (int nt = 0; nt < 2; nt++) {
                mma_f16(d[nt][mt], ah[nt], bh0, bh1);
                mma_f16(d[nt][mt], ah[nt], bl0, bl1);
            }
        }
    }
    __syncthreads();

    if (MODE == 0 || MODE == 1) {
        float2 w1c[8], w2c[8], gbc[8];
#pragma unroll
        for (int mt = 0; mt < 8; mt++) {
            int d2 = dc * 64 + mt * 8 + tig * 2;
            w1c[mt] = *reinterpret_cast<const float2 *>(&w1[kd * DD + d2]);
            w2c[mt] = *reinterpret_cast<const float2 *>(&w2[kd * DD + d2]);
            gbc[mt] = *reinterpret_cast<const float2 *>(&gb[kd * DD + d2]);
        }
#pragma unroll
        for (int nt = 0; nt < 2; nt++)
#pragma unroll
            for (int hf = 0; hf < 2; hf++) {
                int row = nr * 32 + nt * 16 + g + hf * 8;
                int n = n0 + row;
                float s = g_rsA[(size_t)bk * NN + n];
                size_t yb = ((size_t)bk * NN + n) * DD;
#pragma unroll
                for (int mt = 0; mt < 8; mt++) {
                    int d2 = dc * 64 + mt * 8 + tig * 2;
                    float2 yo = *reinterpret_cast<const float2 *>(&g_y[yb + d2]);
                    float dl0 = s * d[nt][mt][hf * 2];
                    float dl1 = s * d[nt][mt][hf * 2 + 1];
                    float g0 = sigmoidf(w1c[mt].x * yo.x + w2c[mt].x * dl0 + gbc[mt].x);
                    float g1 = sigmoidf(w1c[mt].y * yo.y + w2c[mt].y * dl1 + gbc[mt].y);
                    float2 yn = make_float2(yo.x + g0 * dl0, yo.y + g1 * dl1);
                    if (MODE == 0) {
                        *reinterpret_cast<float2 *>(&g_y[yb + d2]) = yn;
                    } else {
                        float2 sd = *reinterpret_cast<const float2 *>(
                            &seed[((size_t)b * NN + n) * DD + d2]);
                        *reinterpret_cast<float2 *>(
                            &out[OFF_YEM + (((size_t)b * NN + n) * NB + kd) * DD + d2]) =
                            make_float2(yn.x - sd.x, yn.y - sd.y);
                    }
                }
            }
    } else {
#pragma unroll
        for (int nt = 0; nt < 2; nt++)
#pragma unroll
            for (int hf = 0; hf < 2; hf++) {
                int row = nr * 32 + nt * 16 + g + hf * 8;
                int n = n0 + row;
                float s = g_rsA[(size_t)bk * NN + n];
                size_t wb = ((size_t)b * NN + n) * DD;
                float p = 0.f;
#pragma unroll
                for (int mt = 0; mt < 8; mt++) {
                    int d2 = dc * 64 + mt * 8 + tig * 2;
                    float2 wv = *reinterpret_cast<const float2 *>(&wcand[wb + d2]);
                    float r0 = wv.x - s * d[nt][mt][hf * 2];
                    float r1 = wv.y - s * d[nt][mt][hf * 2 + 1];
                    p += r0 * r0 + r1 * r1;
                }
                p += __shfl_xor_sync(0xffffffffu, p, 1);
                p += __shfl_xor_sync(0xffffffffu, p, 2);
                if (tig == 0) PSQ[row * 2 + dc] = p;
            }
        __syncthreads();
        if (tid < 128) {
            int n = n0 + tid;
            float nv = 0.5f * g_surp[b * NN + n] +
                       0.5f * sqrtf(PSQ[tid * 2] + PSQ[tid * 2 + 1]);
            NV[tid] = nv;
            g_novp[(size_t)bk * NN + n] = nv * g_rsR[(size_t)bk * NN + n];
        }
        __syncthreads();
#pragma unroll
        for (int nt = 0; nt < 2; nt++)
#pragma unroll
            for (int hf = 0; hf < 2; hf++) {
                int row = nr * 32 + nt * 16 + g + hf * 8;
                int n = n0 + row;
                float nv = NV[row];
                size_t wb = ((size_t)b * NN + n) * DD;
                size_t ob = OFF_DEM + (((size_t)b * NN + n) * NB + kd) * DD;
#pragma unroll
                for (int mt = 0; mt < 8; mt++) {
                    int d2 = dc * 64 + mt * 8 + tig * 2;
                    float2 wv = *reinterpret_cast<const float2 *>(&wcand[wb + d2]);
                    *reinterpret_cast<float2 *>(&out[ob + d2]) =
                        make_float2(nv * wv.x, nv * wv.y);
                }
            }
    }
}

// ---------------- repack (R14-proven) ------------------------------------------------
__global__ __launch_bounds__(256) void repack_kernel() {
    __shared__ uint32_t t[64][68];
    __shared__ float nov[64];
    int bk = blockIdx.y, mt4 = blockIdx.x;
    int tid = threadIdx.x;
    int mp = tid >> 2, jq = tid & 3;
    int m0 = mt4 * 128, mp0 = mt4 * 64;
    size_t rbase = (size_t)bk * MM * (NN / 2);
    float s0 = 0.f, s1 = 0.f;

    for (int nc = 0; nc < 16; nc++) {
        int n0 = nc * 64;
#pragma unroll
        for (int i = 0; i < 4; i++) {
            int f = tid + i * 256;
            int row = f >> 4, q = f & 15;
            *reinterpret_cast<uint4 *>(&t[row][q * 4]) =
                *reinterpret_cast<const uint4 *>(
                    &g_route16[((size_t)bk * NN + n0 + row) * 256 + mp0 + q * 4]);
        }
        if (tid < 64) nov[tid] = g_novp[(size_t)bk * NN + n0 + tid];
        __syncthreads();
#pragma unroll
        for (int i = 0; i < 8; i++) {
            int j = jq + i * 4;
            __half2 h0 = *reinterpret_cast<__half2 *>(&t[2 * j][mp]);
            __half2 h1 = *reinterpret_cast<__half2 *>(&t[2 * j + 1][mp]);
            __half2 lo = __lows2half2(h0, h1);
            __half2 hi = __highs2half2(h0, h1);
            float nv0 = nov[2 * j], nv1 = nov[2 * j + 1];
            __half2 nv2 = __floats2half2_rn(nv0, nv1);
            __half2 olo = __hmul2(lo, nv2);
            __half2 ohi = __hmul2(hi, nv2);
            size_t jg = n0 / 2 + j;
            g_routeT[rbase + (size_t)(m0 + 2 * mp) * 512 + jg] =
                *reinterpret_cast<uint32_t *>(&olo);
            g_routeT[rbase + (size_t)(m0 + 2 * mp + 1) * 512 + jg] =
                *reinterpret_cast<uint32_t *>(&ohi);
            float2 flo = __half22float2(lo), fhi = __half22float2(hi);
            s0 += nv0 * flo.x + nv1 * flo.y;
            s1 += nv0 * fhi.x + nv1 * fhi.y;
        }
        __syncthreads();
    }
    s0 += __shfl_xor_sync(0xffffffffu, s0, 1);
    s0 += __shfl_xor_sync(0xffffffffu, s0, 2);
    s1 += __shfl_xor_sync(0xffffffffu, s1, 1);
    s1 += __shfl_xor_sync(0xffffffffu, s1, 2);
    if (jq == 0) {
        g_swr[bk * MM + m0 + 2 * mp] = s0;
        g_swr[bk * MM + m0 + 2 * mp + 1] = s1;
    }
}

// ---------------- update_K/V: pure fp16 packed GEMM (R14-proven) ---------------------
#define U2_NH   1280
#define U2_NL   3840
#define U2_CH   6400
#define U2_CL   8960
#define U2_STAGE 11520
#define U2_BYTES (2 * U2_STAGE * 4)

__global__ __launch_bounds__(256, 2) void updkv_mma_kernel() {
    extern __shared__ __align__(16) float sm[];
    uint32_t *smU = reinterpret_cast<uint32_t *>(sm);
    uint32_t sb = smem_u32(sm);

    int bk = blockIdx.y, b = bk >> 3;
    int m0 = blockIdx.x * 64;
    int tid = threadIdx.x, w = tid >> 5, lane = tid & 31;
    int mr = w & 3, dc = w >> 2;
    int g = lane >> 2, tig = lane & 3;

    const uint32_t *RTg = g_routeT + (size_t)bk * MM * 512;
    const uint32_t *NHg = g_WnTh + (size_t)b * DD * 512;
    const uint32_t *NLg = g_WnTl + (size_t)b * DD * 512;
    const uint32_t *CHg = g_WcTh + (size_t)b * DD * 512;
    const uint32_t *CLg = g_WcTl + (size_t)b * DD * 512;

    float dK[8][4], dV[8][4];
#pragma unroll
    for (int mt = 0; mt < 8; mt++)
#pragma unroll
        for (int c = 0; c < 4; c++) { dK[mt][c] = 0.f; dV[mt][c] = 0.f; }

    auto prefetch = [&](int nc, int st) {
        int base = st * U2_STAGE;
        {
            int row = tid >> 2, q = tid & 3;
            cp_async16(sb + (base + row * 20 + q * 4) * 4,
                       RTg + (size_t)(m0 + row) * 512 + nc * 16 + q * 4);
        }
#pragma unroll
        for (int i = 0; i < 2; i++) {
            int f = tid + i * 256;
            int row = f >> 2, q = f & 3;
            size_t src = (size_t)row * 512 + nc * 16 + q * 4;
            uint32_t dst = (row * 20 + q * 4) * 4;
            cp_async16(sb + (base + U2_NH) * 4 + dst, NHg + src);
            cp_async16(sb + (base + U2_NL) * 4 + dst, NLg + src);
            cp_async16(sb + (base + U2_CH) * 4 + dst, CHg + src);
            cp_async16(sb + (base + U2_CL) * 4 + dst, CLg + src);
        }
        CP_COMMIT();
    };

    prefetch(0, 0);
    for (int nc = 0; nc < 32; nc++) {
        int st = nc & 1;
        if (nc < 31) { prefetch(nc + 1, st ^ 1); CP_WAIT(1); }
        else         { CP_WAIT(0); }
        __syncthreads();
        int base = st * U2_STAGE;
        const uint32_t *RT = smU + base;
        const uint32_t *NH = smU + base + U2_NH;
        const uint32_t *NL = smU + base + U2_NL;
        const uint32_t *CH = smU + base + U2_CH;
        const uint32_t *CL = smU + base + U2_CL;
#pragma unroll
        for (int ks = 0; ks < 2; ks++) {
            int k0 = ks * 8;
            int ar = mr * 16 + g;
            uint32_t A[4];
            A[0] = RT[ar * 20 + k0 + tig];
            A[1] = RT[(ar + 8) * 20 + k0 + tig];
            A[2] = RT[ar * 20 + k0 + tig + 4];
            A[3] = RT[(ar + 8) * 20 + k0 + tig + 4];
#pragma unroll
            for (int mt = 0; mt < 8; mt++) {
                int dcol = dc * 64 + mt * 8 + g;
                uint32_t nh0 = NH[dcol * 20 + k0 + tig];
                uint32_t nh1 = NH[dcol * 20 + k0 + tig + 4];
                uint32_t nl0 = NL[dcol * 20 + k0 + tig];
                uint32_t nl1 = NL[dcol * 20 + k0 + tig + 4];
                uint32_t ch0 = CH[dcol * 20 + k0 + tig];
                uint32_t ch1 = CH[dcol * 20 + k0 + tig + 4];
                uint32_t cl0 = CL[dcol * 20 + k0 + tig];
                uint32_t cl1 = CL[dcol * 20 + k0 + tig + 4];
                mma_f16(dK[mt], A, nh0, nh1);
                mma_f16(dK[mt], A, nl0, nl1);
                mma_f16(dV[mt], A, ch0, ch1);
                mma_f16(dV[mt], A, cl0, cl1);
            }
        }
        __syncthreads();
    }

#pragma unroll
    for (int mt = 0; mt < 8; mt++) {
        int m_row = m0 + mr * 16 + g;
        int d2 = dc * 64 + mt * 8 + tig * 2;
        size_t o0 = ((size_t)bk * MM + m_row) * DD + d2;
        size_t o1 = ((size_t)bk * MM + m_row + 8) * DD + d2;
        *reinterpret_cast<float2 *>(&g_updK[o0]) = make_float2(dK[mt][0], dK[mt][1]);
        *reinterpret_cast<float2 *>(&g_updK[o1]) = make_float2(dK[mt][2], dK[mt][3]);
        *reinterpret_cast<float2 *>(&g_updV[o0]) = make_float2(dV[mt][0], dV[mt][1]);
        *reinterpret_cast<float2 *>(&g_updV[o1]) = make_float2(dV[mt][2], dV[mt][3]);
    }
}

// ---------------- final ---------------------------------------------------------------
__global__ __launch_bounds__(256) void final_kernel(
    const float *__restrict__ emK, const float *__restrict__ emV,
    const float *__restrict__ emS, const float *__restrict__ emAge,
    const float *__restrict__ gem, float *__restrict__ out) {
    int bk = blockIdx.x, b = bk >> 3, k = bk & 7;
    int tid = threadIdx.x, warp = tid >> 5, lane = tid & 31;
    float ge = gem[b * NB + k];
    const float invN = 1.f / (float)NN;

    for (int m = warp; m < MM; m += 8) {
        float swv = g_swr[bk * MM + m];
        float denom = fmaxf(swv, 1e-8f);
        float alpha = fminf(ge * swv * invN, 1.f);
        float oma = 1.f - alpha;
        float idn = 1.f / denom;
        size_t off = ((size_t)bk * MM + m) * DD + lane * 4;
        float4 uk = *reinterpret_cast<const float4 *>(&g_updK[off]);
        uk.x *= idn; uk.y *= idn; uk.z *= idn; uk.w *= idn;
        float sq = uk.x * uk.x + uk.y * uk.y + uk.z * uk.z + uk.w * uk.w;
#pragma unroll
        for (int o = 16; o; o >>= 1) sq += __shfl_xor_sync(0xffffffffu, sq, o);
        float inv = 1.f / fmaxf(sqrtf(sq), 1e-12f);
        float ai = alpha * inv;
        float4 ek = *reinterpret_cast<const float4 *>(&emK[off]);
        *reinterpret_cast<float4 *>(&out[OFF_K + off]) =
            make_float4(oma * ek.x + ai * uk.x, oma * ek.y + ai * uk.y,
                        oma * ek.z + ai * uk.z, oma * ek.w + ai * uk.w);
        float4 uv = *reinterpret_cast<const float4 *>(&g_updV[off]);
        uv.x *= idn; uv.y *= idn; uv.z *= idn; uv.w *= idn;
        float4 ev = *reinterpret_cast<const float4 *>(&emV[off]);
        *reinterpret_cast<float4 *>(&out[OFF_V + off]) =
            make_float4(oma * ev.x + alpha * uv.x, oma * ev.y + alpha * uv.y,
                        oma * ev.z + alpha * uv.z, oma * ev.w + alpha * uv.w);
    }

    __shared__ float red[8];
    __shared__ float stot;
    float part = 0.f, sn[2], al[2];
#pragma unroll
    for (int i = 0; i < 2; i++) {
        int m = tid + i * 256;
        float swv = g_swr[bk * MM + m];
        al[i] = fminf(ge * swv * invN, 1.f);
        float v = emS[bk * MM + m] + al[i];
        v = fminf(fmaxf(v, 0.f), 3.0f);
        sn[i] = v; part += v;
    }
#pragma unroll
    for (int o = 16; o; o >>= 1) part += __shfl_xor_sync(0xffffffffu, part, o);
    if (lane == 0) red[warp] = part;
    __syncthreads();
    if (tid == 0) {
        float t = 0.f;
        for (int i = 0; i < 8; i++) t += red[i];
        stot = t;
    }
    __syncthreads();
    float scale = fminf(1.f, 32.0f / fmaxf(stot, 1e-8f));
#pragma unroll
    for (int i = 0; i < 2; i++) {
        int m = tid + i * 256;
        out[OFF_S + bk * MM + m] = sn[i] * scale;
        out[OFF_AGE + bk * MM + m] = emAge[bk * MM + m] * (1.f - al[i]);
    }
}

// ---------------- launcher --------------------------------------------------------------
extern "C" void kernel_launch(void *const *d_in, const int *in_sizes, int n_in,
                              void *d_out, int out_size) {
    const float *seed     = (const float *)d_in[0];
    const float *wcand    = (const float *)d_in[1];
    const float *surprise = (const float *)d_in[2];
    const float *gem      = (const float *)d_in[3];
    const float *emK      = (const float *)d_in[4];
    const float *emV      = (const float *)d_in[5];
    const float *emS      = (const float *)d_in[6];
    const float *emAge    = (const float *)d_in[7];
    const float *w1       = (const float *)d_in[8];
    const float *w2       = (const float *)d_in[9];
    const float *gb       = (const float *)d_in[10];
    const float *rtau     = (const float *)d_in[11];
    const float *rtauw    = (const float *)d_in[12];
    float *out = (float *)d_out;

    cudaFuncSetAttribute(scores_mma_kernel<0>,
                         cudaFuncAttributeMaxDynamicSharedMemorySize, S4_BYTES);
    cudaFuncSetAttribute(scores_mma_kernel<1>,
                         cudaFuncAttributeMaxDynamicSharedMemorySize, S4_BYTES);
    cudaFuncSetAttribute(av_mma_kernel<0>,
                         cudaFuncAttributeMaxDynamicSharedMemorySize, AV_BYTES);
    cudaFuncSetAttribute(av_mma_kernel<1>,
                         cudaFuncAttributeMaxDynamicSharedMemorySize, AV_BYTES);
    cudaFuncSetAttribute(av_mma_kernel<2>,
                         cudaFuncAttributeMaxDynamicSharedMemorySize, AV_BYTES);
    cudaFuncSetAttribute(updkv_mma_kernel,
                         cudaFuncAttributeMaxDynamicSharedMemorySize, U2_BYTES);

    dim3 gS(32, 64), gA(8, 64), gU(8, 64);
    dim3 gT(16, 4, 64), bT(32, 8);
    dim3 gW(32, 4, 8);

    kpack_kernel<<<4096, 256>>>(emK);
    transpose_v_kernel<<<gT, bT>>>(emV);
    init_y_kernel<<<8192, 256>>>(seed);
    wnorm_kernel<<<8192, 128>>>(wcand, surprise);
    wtpack_kernel<<<gW, bT>>>(wcand);

    scores_mma_kernel<0><<<gS, 256, S4_BYTES>>>(emS, rtau, rtauw);
    av_mma_kernel<0><<<gA, 256, AV_BYTES>>>(w1, w2, gb, seed, wcand, out);
    scores_mma_kernel<0><<<gS, 256, S4_BYTES>>>(emS, rtau, rtauw);
    av_mma_kernel<1><<<gA, 256, AV_BYTES>>>(w1, w2, gb, seed, wcand, out);

    scores_mma_kernel<1><<<gS, 256, S4_BYTES>>>(emS, rtau, rtauw);
    av_mma_kernel<2><<<gA, 256, AV_BYTES>>>(w1, w2, gb, seed, wcand, out);

    repack_kernel<<<dim3(4, 64), 256>>>();
    updkv_mma_kernel<<<gU, 256, U2_BYTES>>>();
    final_kernel<<<64, 256>>>(emK, emV, emS, emAge, gem, out);
}

// round 17
// speedup vs baseline: 1.1852x; 1.0102x over previous
#include <cuda_runtime.h>
#include <cuda_fp16.h>
#include <math.h>
#include <stdint.h>

#define BSZ 8
#define NB  8
#define MM  512
#define DD  128
#define NN  1024
#define NBK 64
#define NEGV (-1e30f)

#define OFF_YEM 0
#define OFF_DEM 8388608
#define OFF_K   16777216
#define OFF_V   20971520
#define OFF_S   25165824
#define OFF_AGE 25198592

// ---------------- scratch -----------------------------------------------------
__device__ float g_y[NBK * NN * DD];
__device__ uint32_t g_attn16[NBK * NN * (MM / 2)];
__device__ uint32_t g_route16[NBK * NN * (MM / 2)];
__device__ uint32_t g_routeT[NBK * MM * (NN / 2)];
__device__ float g_wnorm[BSZ * NN * DD];
__device__ float g_surp[BSZ * NN];
__device__ float g_novp[NBK * NN];
__device__ float g_rsA[NBK * NN];
__device__ float g_rsR[NBK * NN];
__device__ float g_updK[NBK * MM * DD];
__device__ float g_updV[NBK * MM * DD];
__device__ float g_swr[NBK * MM];
__device__ uint32_t g_Vth[NBK * DD * (MM / 2)];
__device__ uint32_t g_Vtl[NBK * DD * (MM / 2)];
__device__ uint32_t g_WnTh[BSZ * DD * (NN / 2)];
__device__ uint32_t g_WnTl[BSZ * DD * (NN / 2)];
__device__ uint32_t g_WcTh[BSZ * DD * (NN / 2)];
__device__ uint32_t g_WcTl[BSZ * DD * (NN / 2)];
__device__ uint32_t g_KpackH[NBK * 8 * MM * 8];
__device__ uint32_t g_KpackL[NBK * 8 * MM * 8];

// ---------------- helpers -----------------------------------------------------
__device__ __forceinline__ float softplusf(float x) {
    return (x > 20.f) ? x : log1pf(expf(x));
}
__device__ __forceinline__ float sigmoidf(float x) {
    return 1.f / (1.f + __expf(-x));
}
__device__ __forceinline__ uint32_t smem_u32(const void *p) {
    uint32_t a;
    asm("{ .reg .u64 t; cvta.to.shared.u64 t, %1; cvt.u32.u64 %0, t; }"
        : "=r"(a) : "l"(p));
    return a;
}
__device__ __forceinline__ void cp_async16(uint32_t saddr, const void *gaddr) {
    asm volatile("cp.async.cg.shared.global [%0], [%1], 16;"
                 :: "r"(saddr), "l"(gaddr) : "memory");
}
#define CP_COMMIT() asm volatile("cp.async.commit_group;" ::: "memory")
#define CP_WAIT(n)  asm volatile("cp.async.wait_group %0;" :: "n"(n) : "memory")

__device__ __forceinline__ void mma_f16(float d[4], const uint32_t a[4],
                                        uint32_t b0, uint32_t b1) {
    asm volatile(
        "mma.sync.aligned.m16n8k16.row.col.f32.f16.f16.f32 "
        "{%0,%1,%2,%3}, {%4,%5,%6,%7}, {%8,%9}, {%0,%1,%2,%3};"
        : "+f"(d[0]), "+f"(d[1]), "+f"(d[2]), "+f"(d[3])
        : "r"(a[0]), "r"(a[1]), "r"(a[2]), "r"(a[3]), "r"(b0), "r"(b1));
}
__device__ __forceinline__ void split4(float4 x, uint32_t &h01, uint32_t &h23,
                                       uint32_t &l01, uint32_t &l23) {
    __half2 a = __float22half2_rn(make_float2(x.x, x.y));
    __half2 b = __float22half2_rn(make_float2(x.z, x.w));
    float2 fa = __half22float2(a);
    float2 fb = __half22float2(b);
    __half2 la = __float22half2_rn(make_float2(x.x - fa.x, x.y - fa.y));
    __half2 lb = __float22half2_rn(make_float2(x.z - fb.x, x.w - fb.y));
    h01 = *reinterpret_cast<uint32_t *>(&a);
    h23 = *reinterpret_cast<uint32_t *>(&b);
    l01 = *reinterpret_cast<uint32_t *>(&la);
    l23 = *reinterpret_cast<uint32_t *>(&lb);
}
__device__ __forceinline__ void split2(float x, float y, uint32_t &h, uint32_t &l) {
    __half2 a = __float22half2_rn(make_float2(x, y));
    float2 fa = __half22float2(a);
    __half2 la = __float22half2_rn(make_float2(x - fa.x, y - fa.y));
    h = *reinterpret_cast<uint32_t *>(&a);
    l = *reinterpret_cast<uint32_t *>(&la);
}
__device__ __forceinline__ uint32_t pack2(float x, float y) {
    __half2 a = __float22half2_rn(make_float2(x, y));
    return *reinterpret_cast<uint32_t *>(&a);
}

// ---------------- em_K -> packed swizzled chunks -----------------------------------
__global__ void kpack_kernel(const float *__restrict__ emK) {
    int i = blockIdx.x * 256 + threadIdx.x;
    int bk = i >> 14;
    int rem = i & 16383;
    int m = rem >> 5, f4 = rem & 31;
    float4 x = reinterpret_cast<const float4 *>(emK)[i];
    uint32_t h01, h23, l01, l23;
    split4(x, h01, h23, l01, l23);
    int kc = f4 >> 2, qw = (f4 & 3) * 2;
    int qwp = qw ^ (((m >> 2) & 1) << 2);
    size_t off = ((size_t)(bk * 8 + kc) * 512 + m) * 8 + qwp;
    *reinterpret_cast<uint2 *>(&g_KpackH[off]) = make_uint2(h01, h23);
    *reinterpret_cast<uint2 *>(&g_KpackL[off]) = make_uint2(l01, l23);
}

// ---------------- V transpose + pack ---------------------------------------------
__global__ void transpose_v_kernel(const float *__restrict__ emV) {
    __shared__ float t[32][33];
    int bk = blockIdx.z;
    int m0 = blockIdx.x * 32, d0 = blockIdx.y * 32;
    int x = threadIdx.x, y0 = threadIdx.y;
#pragma unroll
    for (int yy = 0; yy < 32; yy += 8)
        t[y0 + yy][x] = emV[((size_t)bk * MM + m0 + y0 + yy) * DD + d0 + x];
    __syncthreads();
    int px = x & 15, hl = x >> 4;
#pragma unroll
    for (int yy = 0; yy < 32; yy += 8) {
        int dl = y0 + yy;
        float v0 = t[2 * px][dl], v1 = t[2 * px + 1][dl];
        uint32_t h, l;
        split2(v0, v1, h, l);
        size_t idx = ((size_t)bk * DD + d0 + dl) * (MM / 2) + m0 / 2 + px;
        if (hl == 0) g_Vth[idx] = h;
        else         g_Vtl[idx] = l;
    }
}

// ---------------- wnorm/wcand transpose + pack --------------------------------------
__global__ void wtpack_kernel(const float *__restrict__ wcand) {
    __shared__ float t1[32][33], t2[32][33];
    int b = blockIdx.z;
    int n0 = blockIdx.x * 32, d0 = blockIdx.y * 32;
    int x = threadIdx.x, y0 = threadIdx.y;
#pragma unroll
    for (int yy = 0; yy < 32; yy += 8) {
        size_t src = ((size_t)b * NN + n0 + y0 + yy) * DD + d0 + x;
        t1[y0 + yy][x] = g_wnorm[src];
        t2[y0 + yy][x] = wcand[src];
    }
    __syncthreads();
    int px = x & 15, hl = x >> 4;
#pragma unroll
    for (int yy = 0; yy < 32; yy += 8) {
        int dl = y0 + yy;
        size_t idx = ((size_t)b * DD + d0 + dl) * (NN / 2) + n0 / 2 + px;
        uint32_t h, l;
        split2(t1[2 * px][dl], t1[2 * px + 1][dl], h, l);
        if (hl == 0) g_WnTh[idx] = h; else g_WnTl[idx] = l;
        split2(t2[2 * px][dl], t2[2 * px + 1][dl], h, l);
        if (hl == 0) g_WcTh[idx] = h; else g_WcTl[idx] = l;
    }
}

// ---------------- y init ----------------------------------------------------------
__global__ void init_y_kernel(const float *__restrict__ seed) {
    int i = blockIdx.x * 256 + threadIdx.x;
    int bk = i >> 15;
    int rem = i & 32767;
    int b = bk >> 3;
    reinterpret_cast<float4 *>(g_y)[i] =
        reinterpret_cast<const float4 *>(seed)[b * 32768 + rem];
}

// ---------------- w_norm + surprise magnitude -------------------------------------
__global__ void wnorm_kernel(const float *__restrict__ wc,
                             const float *__restrict__ sp) {
    int row = blockIdx.x;
    int tid = threadIdx.x;
    float w = wc[row * DD + tid];
    float s = sp[row * DD + tid];
    float a = w * w, bb = s * s;
#pragma unroll
    for (int o = 16; o; o >>= 1) {
        a  += __shfl_xor_sync(0xffffffffu, a, o);
        bb += __shfl_xor_sync(0xffffffffu, bb, o);
    }
    __shared__ float ra[4], rb[4];
    if ((tid & 31) == 0) { ra[tid >> 5] = a; rb[tid >> 5] = bb; }
    __syncthreads();
    float na = ra[0] + ra[1] + ra[2] + ra[3];
    float nb = rb[0] + rb[1] + rb[2] + rb[3];
    g_wnorm[row * DD + tid] = w / fmaxf(sqrtf(na), 1e-12f);
    if (tid == 0) g_surp[row] = sqrtf(nb);
}

// ---------------- scores v4 (R16-proven): 256 thr, 32n x 512m, 2 blocks/SM ----------
#define S4_YH    16384
#define S4_YL    19456
#define S4_RED   22528
#define S4_SSV   22784
#define S4_WORDS 23296
#define S4_BYTES (S4_WORDS * 4)

template <int MODE>
__global__ __launch_bounds__(256, 2) void scores_mma_kernel(
    const float *__restrict__ emS,
    const float *__restrict__ rtau, const float *__restrict__ rtauw) {
    extern __shared__ __align__(16) float sm[];
    uint32_t *smU = reinterpret_cast<uint32_t *>(sm);
    float *RED = sm + S4_RED;
    float *SSV = sm + S4_SSV;
    uint32_t sb = smem_u32(sm);

    int bk = blockIdx.y, b = bk >> 3, k = bk & 7;
    int n0 = blockIdx.x * 32;
    int tid = threadIdx.x, wc = tid >> 5, lane = tid & 31;
    int g = lane >> 2, tig = lane & 3;
    int sm4 = ((g >> 2) & 1) * 4;

    const float *Yb = (MODE == 0) ? (g_y + (size_t)bk * NN * DD)
                                  : (g_wnorm + (size_t)b * NN * DD);
    const uint32_t *KHg = g_KpackH + (size_t)bk * 8 * 512 * 8;
    const uint32_t *KLg = g_KpackL + (size_t)bk * 8 * 512 * 8;

    float d[2][8][4];
#pragma unroll
    for (int nt = 0; nt < 2; nt++)
#pragma unroll
        for (int mt = 0; mt < 8; mt++)
#pragma unroll
            for (int c = 0; c < 4; c++) d[nt][mt][c] = 0.f;

    auto prefetch = [&](int kc, int st) {
#pragma unroll
        for (int i = 0; i < 4; i++) {
            int f = tid + i * 256;
            cp_async16(sb + (st * 8192 + f * 4) * 4,
                       KHg + (size_t)kc * 4096 + f * 4);
            cp_async16(sb + (st * 8192 + 4096 + f * 4) * 4,
                       KLg + (size_t)kc * 4096 + f * 4);
        }
        CP_COMMIT();
    };

    prefetch(0, 0);
#pragma unroll
    for (int i = 0; i < 4; i++) {
        int f = tid + i * 256;
        int row = f >> 5, q = f & 31;
        float4 x = *reinterpret_cast<const float4 *>(
            &Yb[(size_t)(n0 + row) * DD + q * 4]);
        uint32_t h01, h23, l01, l23;
        split4(x, h01, h23, l01, l23);
        int kc = q >> 2, qw = (q & 3) * 2;
        *reinterpret_cast<uint2 *>(&smU[S4_YH + kc * 384 + row * 12 + qw]) =
            make_uint2(h01, h23);
        *reinterpret_cast<uint2 *>(&smU[S4_YL + kc * 384 + row * 12 + qw]) =
            make_uint2(l01, l23);
    }

    for (int kc = 0; kc < 8; kc++) {
        int st = kc & 1;
        CP_WAIT(0);
        __syncthreads();
        if (kc + 1 < 8) prefetch(kc + 1, st ^ 1);
        uint32_t ah[2][4], al[2][4];
        int yh = S4_YH + kc * 384, yl = S4_YL + kc * 384;
#pragma unroll
        for (int nt = 0; nt < 2; nt++) {
            int r0 = nt * 16 + g;
            ah[nt][0] = smU[yh + r0 * 12 + tig];
            ah[nt][1] = smU[yh + (r0 + 8) * 12 + tig];
            ah[nt][2] = smU[yh + r0 * 12 + tig + 4];
            ah[nt][3] = smU[yh + (r0 + 8) * 12 + tig + 4];
            al[nt][0] = smU[yl + r0 * 12 + tig];
            al[nt][1] = smU[yl + (r0 + 8) * 12 + tig];
            al[nt][2] = smU[yl + r0 * 12 + tig + 4];
            al[nt][3] = smU[yl + (r0 + 8) * 12 + tig + 4];
        }
        int kh = st * 8192, kl = st * 8192 + 4096;
#pragma unroll
        for (int mt = 0; mt < 8; mt++) {
            int m = wc * 64 + mt * 8 + g;
            uint32_t bh0 = smU[kh + m * 8 + sm4 + tig];
            uint32_t bh1 = smU[kh + m * 8 + (4 - sm4) + tig];
            uint32_t bl0 = smU[kl + m * 8 + sm4 + tig];
            uint32_t bl1 = smU[kl + m * 8 + (4 - sm4) + tig];
#pragma unroll
            for (int nt = 0; nt < 2; nt++) {
                mma_f16(d[nt][mt], ah[nt], bh0, bh1);
                mma_f16(d[nt][mt], ah[nt], bl0, bl1);
                mma_f16(d[nt][mt], al[nt], bh0, bh1);
            }
        }
    }
    __syncthreads();

    // ---- epilogue ----------------------------------------------------------------
    float sv0 = emS[bk * MM + tid];
    float sv1 = emS[bk * MM + 256 + tid];
    SSV[tid] = sv0;
    SSV[256 + tid] = sv1;
    int hasAny = __syncthreads_or(sv0 > 0.f || sv1 > 0.f);

    bool act[8][2];
#pragma unroll
    for (int mt = 0; mt < 8; mt++) {
        int c = wc * 64 + mt * 8 + tig * 2;
        act[mt][0] = SSV[c] > 0.f;
        act[mt][1] = SSV[c + 1] > 0.f;
    }
    float inv_tau  = 1.f / (softplusf(rtau[k]) + 0.1f);
    float inv_tauw = 1.f / (softplusf(rtauw[k]) + 0.1f);

#pragma unroll
    for (int nt = 0; nt < 2; nt++) {
        float m0 = NEGV, m1 = NEGV;
#pragma unroll
        for (int mt = 0; mt < 8; mt++) {
            if (act[mt][0]) { m0 = fmaxf(m0, d[nt][mt][0]); m1 = fmaxf(m1, d[nt][mt][2]); }
            if (act[mt][1]) { m0 = fmaxf(m0, d[nt][mt][1]); m1 = fmaxf(m1, d[nt][mt][3]); }
        }
#pragma unroll
        for (int o = 1; o <= 2; o <<= 1) {
            m0 = fmaxf(m0, __shfl_xor_sync(0xffffffffu, m0, o));
            m1 = fmaxf(m1, __shfl_xor_sync(0xffffffffu, m1, o));
        }
        if (tig == 0) {
            RED[(nt * 16 + g) * 8 + wc] = m0;
            RED[(nt * 16 + g + 8) * 8 + wc] = m1;
        }
    }
    __syncthreads();
    float gmx[2][2];
#pragma unroll
    for (int nt = 0; nt < 2; nt++)
#pragma unroll
        for (int h = 0; h < 2; h++) {
            int r = nt * 16 + g + h * 8;
            float m = RED[r * 8];
#pragma unroll
            for (int i = 1; i < 8; i++) m = fmaxf(m, RED[r * 8 + i]);
            gmx[nt][h] = m;
        }
    __syncthreads();

    int np = (MODE == 1) ? 2 : 1;
    for (int p = 0; p < np; p++) {
        float sc = (p == 0) ? inv_tau : inv_tauw;
        uint32_t *op = (p == 0) ? g_attn16 : g_route16;
        float rs[2][2] = {{0.f, 0.f}, {0.f, 0.f}};
#pragma unroll
        for (int nt = 0; nt < 2; nt++) {
            int rlo = n0 + nt * 16 + g;
#pragma unroll
            for (int mt = 0; mt < 8; mt++) {
                float e00, e01, e10, e11;
                if (!hasAny) { e00 = e01 = e10 = e11 = 1.f; }
                else {
                    e00 = act[mt][0] ? __expf((d[nt][mt][0] - gmx[nt][0]) * sc) : 0.f;
                    e01 = act[mt][1] ? __expf((d[nt][mt][1] - gmx[nt][0]) * sc) : 0.f;
                    e10 = act[mt][0] ? __expf((d[nt][mt][2] - gmx[nt][1]) * sc) : 0.f;
                    e11 = act[mt][1] ? __expf((d[nt][mt][3] - gmx[nt][1]) * sc) : 0.f;
                }
                rs[nt][0] += e00 + e01;
                rs[nt][1] += e10 + e11;
                size_t w0 = ((size_t)bk * NN + rlo) * 256 + wc * 32 + mt * 4 + tig;
                op[w0] = pack2(e00, e01);
                op[w0 + 8 * 256] = pack2(e10, e11);
            }
#pragma unroll
            for (int o = 1; o <= 2; o <<= 1) {
                rs[nt][0] += __shfl_xor_sync(0xffffffffu, rs[nt][0], o);
                rs[nt][1] += __shfl_xor_sync(0xffffffffu, rs[nt][1], o);
            }
            if (tig == 0) {
                RED[(nt * 16 + g) * 8 + wc] = rs[nt][0];
                RED[(nt * 16 + g + 8) * 8 + wc] = rs[nt][1];
            }
        }
        __syncthreads();
        if (tid < 32) {
            float t = 0.f;
#pragma unroll
            for (int i = 0; i < 8; i++) t += RED[tid * 8 + i];
            size_t nidx = (size_t)bk * NN + n0 + tid;
            if (p == 0) g_rsA[nidx] = hasAny ? (1.f / t) : 0.f;
            else        g_rsR[nidx] = 1.f / t;
        }
        __syncthreads();
    }
}

// ---------------- A@V v2: 128 thr, 64n x 128d, 4 blocks/SM, 3-stage ring -------------
// 4 warps (nr = w&1, dc = w>>1), warp 32n x 64d.
// stage (words, rel st*3840): AH 0 (64x12), VH 768 (128x12), VL 2304 (128x12).
#define A4_PSQ 11520
#define A4_NV 11648
#define A4_WORDS 11712
#define A4_BYTES (A4_WORDS * 4)

template <int MODE>
__global__ __launch_bounds__(128, 4) void av_mma_kernel(
    const float *__restrict__ w1, const float *__restrict__ w2,
    const float *__restrict__ gb, const float *__restrict__ seed,
    const float *__restrict__ wcand, float *__restrict__ out) {
    extern __shared__ __align__(16) float sm[];
    uint32_t *smU = reinterpret_cast<uint32_t *>(sm);
    float *PSQ = sm + A4_PSQ;
    float *NV  = sm + A4_NV;
    uint32_t sb = smem_u32(sm);

    int bk = blockIdx.y, b = bk >> 3, kd = bk & 7;
    int n0 = blockIdx.x * 64;
    int tid = threadIdx.x, w = tid >> 5, lane = tid & 31;
    int nr = w & 1, dc = w >> 1;
    int g = lane >> 2, tig = lane & 3;

    const uint32_t *AHb = g_attn16 + (size_t)bk * NN * 256;
    const uint32_t *VHb = g_Vth + (size_t)bk * DD * 256;
    const uint32_t *VLb = g_Vtl + (size_t)bk * DD * 256;

    float d[2][8][4];
#pragma unroll
    for (int nt = 0; nt < 2; nt++)
#pragma unroll
        for (int mt = 0; mt < 8; mt++)
#pragma unroll
            for (int c = 0; c < 4; c++) d[nt][mt][c] = 0.f;

    auto prefetch = [&](int mc, int st) {
        int base = st * 3840;
        {   // A: 64 rows x 8 words
            int row = tid >> 1, q = tid & 1;
            cp_async16(sb + (base + row * 12 + q * 4) * 4,
                       AHb + (size_t)(n0 + row) * 256 + mc * 8 + q * 4);
        }
#pragma unroll
        for (int i = 0; i < 2; i++) {   // VH/VL: 128 rows x 8 words each
            int f = tid + i * 128;
            int row = f >> 1, q = f & 1;
            uint32_t dst = (row * 12 + q * 4) * 4;
            size_t src = (size_t)row * 256 + mc * 8 + q * 4;
            cp_async16(sb + (base + 768) * 4 + dst, VHb + src);
            cp_async16(sb + (base + 2304) * 4 + dst, VLb + src);
        }
        CP_COMMIT();
    };

    prefetch(0, 0);
    prefetch(1, 1);
    for (int mc = 0; mc < 32; mc++) {
        int st = mc % 3;
        if (mc == 31) { CP_WAIT(0); } else { CP_WAIT(1); }
        __syncthreads();
        if (mc + 2 < 32) prefetch(mc + 2, (mc + 2) % 3);
        int base = st * 3840;
        int ahO = base, vhO = base + 768, vlO = base + 2304;
        uint32_t ah[2][4];
#pragma unroll
        for (int nt = 0; nt < 2; nt++) {
            int r0 = nr * 32 + nt * 16 + g;
            ah[nt][0] = smU[ahO + r0 * 12 + tig];
            ah[nt][1] = smU[ahO + (r0 + 8) * 12 + tig];
            ah[nt][2] = smU[ahO + r0 * 12 + tig + 4];
            ah[nt][3] = smU[ahO + (r0 + 8) * 12 + tig + 4];
        }
#pragma unroll
        for (int mt = 0; mt < 8; mt++) {
            int dr = dc * 64 + mt * 8 + g;
            uint32_t bh0 = smU[vhO + dr * 12 + tig];
            uint32_t bh1 = smU[vhO + dr * 12 + tig + 4];
            uint32_t bl0 = smU[vlO + dr * 12 + tig];
            uint32_t bl1 = smU[vlO + dr * 12 + tig + 4];
#pragma unroll
            for (int nt = 0; nt < 2; nt++) {
                mma_f16(d[nt][mt], ah[nt], bh0, bh1);
                mma_f16(d[nt][mt], ah[nt], bl0, bl1);
            }
        }
    }
    __syncthreads();

    if (MODE == 0 || MODE == 1) {
        float2 w1c[8], w2c[8], gbc[8];
#pragma unroll
        for (int mt = 0; mt < 8; mt++) {
            int d2 = dc * 64 + mt * 8 + tig * 2;
            w1c[mt] = *reinterpret_cast<const float2 *>(&w1[kd * DD + d2]);
            w2c[mt] = *reinterpret_cast<const float2 *>(&w2[kd * DD + d2]);
            gbc[mt] = *reinterpret_cast<const float2 *>(&gb[kd * DD + d2]);
        }
#pragma unroll
        for (int nt = 0; nt < 2; nt++)
#pragma unroll
            for (int hf = 0; hf < 2; hf++) {
                int row = nr * 32 + nt * 16 + g + hf * 8;
                int n = n0 + row;
                float s = g_rsA[(size_t)bk * NN + n];
                size_t yb = ((size_t)bk * NN + n) * DD;
#pragma unroll
                for (int mt = 0; mt < 8; mt++) {
                    int d2 = dc * 64 + mt * 8 + tig * 2;
                    float2 yo = *reinterpret_cast<const float2 *>(&g_y[yb + d2]);
                    float dl0 = s * d[nt][mt][hf * 2];
                    float dl1 = s * d[nt][mt][hf * 2 + 1];
                    float g0 = sigmoidf(w1c[mt].x * yo.x + w2c[mt].x * dl0 + gbc[mt].x);
                    float g1 = sigmoidf(w1c[mt].y * yo.y + w2c[mt].y * dl1 + gbc[mt].y);
                    float2 yn = make_float2(yo.x + g0 * dl0, yo.y + g1 * dl1);
                    if (MODE == 0) {
                        *reinterpret_cast<float2 *>(&g_y[yb + d2]) = yn;
                    } else {
                        float2 sd = *reinterpret_cast<const float2 *>(
                            &seed[((size_t)b * NN + n) * DD + d2]);
                        *reinterpret_cast<float2 *>(
                            &out[OFF_YEM + (((size_t)b * NN + n) * NB + kd) * DD + d2]) =
                            make_float2(yn.x - sd.x, yn.y - sd.y);
                    }
                }
            }
    } else {
#pragma unroll
        for (int nt = 0; nt < 2; nt++)
#pragma unroll
            for (int hf = 0; hf < 2; hf++) {
                int row = nr * 32 + nt * 16 + g + hf * 8;
                int n = n0 + row;
                float s = g_rsA[(size_t)bk * NN + n];
                size_t wb = ((size_t)b * NN + n) * DD;
                float p = 0.f;
#pragma unroll
                for (int mt = 0; mt < 8; mt++) {
                    int d2 = dc * 64 + mt * 8 + tig * 2;
                    float2 wv = *reinterpret_cast<const float2 *>(&wcand[wb + d2]);
                    float r0 = wv.x - s * d[nt][mt][hf * 2];
                    float r1 = wv.y - s * d[nt][mt][hf * 2 + 1];
                    p += r0 * r0 + r1 * r1;
                }
                p += __shfl_xor_sync(0xffffffffu, p, 1);
                p += __shfl_xor_sync(0xffffffffu, p, 2);
                if (tig == 0) PSQ[row * 2 + dc] = p;
            }
        __syncthreads();
        if (tid < 64) {
            int n = n0 + tid;
            float nv = 0.5f * g_surp[b * NN + n] +
                       0.5f * sqrtf(PSQ[tid * 2] + PSQ[tid * 2 + 1]);
            NV[tid] = nv;
            g_novp[(size_t)bk * NN + n] = nv * g_rsR[(size_t)bk * NN + n];
        }
        __syncthreads();
#pragma unroll
        for (int nt = 0; nt < 2; nt++)
#pragma unroll
            for (int hf = 0; hf < 2; hf++) {
                int row = nr * 32 + nt * 16 + g + hf * 8;
                int n = n0 + row;
                float nv = NV[row];
                size_t wb = ((size_t)b * NN + n) * DD;
                size_t ob = OFF_DEM + (((size_t)b * NN + n) * NB + kd) * DD;
#pragma unroll
                for (int mt = 0; mt < 8; mt++) {
                    int d2 = dc * 64 + mt * 8 + tig * 2;
                    float2 wv = *reinterpret_cast<const float2 *>(&wcand[wb + d2]);
                    *reinterpret_cast<float2 *>(&out[ob + d2]) =
                        make_float2(nv * wv.x, nv * wv.y);
                }
            }
    }
}

// ---------------- repack (R14-proven) ------------------------------------------------
__global__ __launch_bounds__(256) void repack_kernel() {
    __shared__ uint32_t t[64][68];
    __shared__ float nov[64];
    int bk = blockIdx.y, mt4 = blockIdx.x;
    int tid = threadIdx.x;
    int mp = tid >> 2, jq = tid & 3;
    int m0 = mt4 * 128, mp0 = mt4 * 64;
    size_t rbase = (size_t)bk * MM * (NN / 2);
    float s0 = 0.f, s1 = 0.f;

    for (int nc = 0; nc < 16; nc++) {
        int n0 = nc * 64;
#pragma unroll
        for (int i = 0; i < 4; i++) {
            int f = tid + i * 256;
            int row = f >> 4, q = f & 15;
            *reinterpret_cast<uint4 *>(&t[row][q * 4]) =
                *reinterpret_cast<const uint4 *>(
                    &g_route16[((size_t)bk * NN + n0 + row) * 256 + mp0 + q * 4]);
        }
        if (tid < 64) nov[tid] = g_novp[(size_t)bk * NN + n0 + tid];
        __syncthreads();
#pragma unroll
        for (int i = 0; i < 8; i++) {
            int j = jq + i * 4;
            __half2 h0 = *reinterpret_cast<__half2 *>(&t[2 * j][mp]);
            __half2 h1 = *reinterpret_cast<__half2 *>(&t[2 * j + 1][mp]);
            __half2 lo = __lows2half2(h0, h1);
            __half2 hi = __highs2half2(h0, h1);
            float nv0 = nov[2 * j], nv1 = nov[2 * j + 1];
            __half2 nv2 = __floats2half2_rn(nv0, nv1);
            __half2 olo = __hmul2(lo, nv2);
            __half2 ohi = __hmul2(hi, nv2);
            size_t jg = n0 / 2 + j;
            g_routeT[rbase + (size_t)(m0 + 2 * mp) * 512 + jg] =
                *reinterpret_cast<uint32_t *>(&olo);
            g_routeT[rbase + (size_t)(m0 + 2 * mp + 1) * 512 + jg] =
                *reinterpret_cast<uint32_t *>(&ohi);
            float2 flo = __half22float2(lo), fhi = __half22float2(hi);
            s0 += nv0 * flo.x + nv1 * flo.y;
            s1 += nv0 * fhi.x + nv1 * fhi.y;
        }
        __syncthreads();
    }
    s0 += __shfl_xor_sync(0xffffffffu, s0, 1);
    s0 += __shfl_xor_sync(0xffffffffu, s0, 2);
    s1 += __shfl_xor_sync(0xffffffffu, s1, 1);
    s1 += __shfl_xor_sync(0xffffffffu, s1, 2);
    if (jq == 0) {
        g_swr[bk * MM + m0 + 2 * mp] = s0;
        g_swr[bk * MM + m0 + 2 * mp + 1] = s1;
    }
}

// ---------------- update_K/V: pure fp16 packed GEMM (R14-proven) ---------------------
#define U2_NH   1280
#define U2_NL   3840
#define U2_CH   6400
#define U2_CL   8960
#define U2_STAGE 11520
#define U2_BYTES (2 * U2_STAGE * 4)

__global__ __launch_bounds__(256, 2) void updkv_mma_kernel() {
    extern __shared__ __align__(16) float sm[];
    uint32_t *smU = reinterpret_cast<uint32_t *>(sm);
    uint32_t sb = smem_u32(sm);

    int bk = blockIdx.y, b = bk >> 3;
    int m0 = blockIdx.x * 64;
    int tid = threadIdx.x, w = tid >> 5, lane = tid & 31;
    int mr = w & 3, dc = w >> 2;
    int g = lane >> 2, tig = lane & 3;

    const uint32_t *RTg = g_routeT + (size_t)bk * MM * 512;
    const uint32_t *NHg = g_WnTh + (size_t)b * DD * 512;
    const uint32_t *NLg = g_WnTl + (size_t)b * DD * 512;
    const uint32_t *CHg = g_WcTh + (size_t)b * DD * 512;
    const uint32_t *CLg = g_WcTl + (size_t)b * DD * 512;

    float dK[8][4], dV[8][4];
#pragma unroll
    for (int mt = 0; mt < 8; mt++)
#pragma unroll
        for (int c = 0; c < 4; c++) { dK[mt][c] = 0.f; dV[mt][c] = 0.f; }

    auto prefetch = [&](int nc, int st) {
        int base = st * U2_STAGE;
        {
            int row = tid >> 2, q = tid & 3;
            cp_async16(sb + (base + row * 20 + q * 4) * 4,
                       RTg + (size_t)(m0 + row) * 512 + nc * 16 + q * 4);
        }
#pragma unroll
        for (int i = 0; i < 2; i++) {
            int f = tid + i * 256;
            int row = f >> 2, q = f & 3;
            size_t src = (size_t)row * 512 + nc * 16 + q * 4;
            uint32_t dst = (row * 20 + q * 4) * 4;
            cp_async16(sb + (base + U2_NH) * 4 + dst, NHg + src);
            cp_async16(sb + (base + U2_NL) * 4 + dst, NLg + src);
            cp_async16(sb + (base + U2_CH) * 4 + dst, CHg + src);
            cp_async16(sb + (base + U2_CL) * 4 + dst, CLg + src);
        }
        CP_COMMIT();
    };

    prefetch(0, 0);
    for (int nc = 0; nc < 32; nc++) {
        int st = nc & 1;
        if (nc < 31) { prefetch(nc + 1, st ^ 1); CP_WAIT(1); }
        else         { CP_WAIT(0); }
        __syncthreads();
        int base = st * U2_STAGE;
        const uint32_t *RT = smU + base;
        const uint32_t *NH = smU + base + U2_NH;
        const uint32_t *NL = smU + base + U2_NL;
        const uint32_t *CH = smU + base + U2_CH;
        const uint32_t *CL = smU + base + U2_CL;
#pragma unroll
        for (int ks = 0; ks < 2; ks++) {
            int k0 = ks * 8;
            int ar = mr * 16 + g;
            uint32_t A[4];
            A[0] = RT[ar * 20 + k0 + tig];
            A[1] = RT[(ar + 8) * 20 + k0 + tig];
            A[2] = RT[ar * 20 + k0 + tig + 4];
            A[3] = RT[(ar + 8) * 20 + k0 + tig + 4];
#pragma unroll
            for (int mt = 0; mt < 8; mt++) {
                int dcol = dc * 64 + mt * 8 + g;
                uint32_t nh0 = NH[dcol * 20 + k0 + tig];
                uint32_t nh1 = NH[dcol * 20 + k0 + tig + 4];
                uint32_t nl0 = NL[dcol * 20 + k0 + tig];
                uint32_t nl1 = NL[dcol * 20 + k0 + tig + 4];
                uint32_t ch0 = CH[dcol * 20 + k0 + tig];
                uint32_t ch1 = CH[dcol * 20 + k0 + tig + 4];
                uint32_t cl0 = CL[dcol * 20 + k0 + tig];
                uint32_t cl1 = CL[dcol * 20 + k0 + tig + 4];
                mma_f16(dK[mt], A, nh0, nh1);
                mma_f16(dK[mt], A, nl0, nl1);
                mma_f16(dV[mt], A, ch0, ch1);
                mma_f16(dV[mt], A, cl0, cl1);
            }
        }
        __syncthreads();
    }

#pragma unroll
    for (int mt = 0; mt < 8; mt++) {
        int m_row = m0 + mr * 16 + g;
        int d2 = dc * 64 + mt * 8 + tig * 2;
        size_t o0 = ((size_t)bk * MM + m_row) * DD + d2;
        size_t o1 = ((size_t)bk * MM + m_row + 8) * DD + d2;
        *reinterpret_cast<float2 *>(&g_updK[o0]) = make_float2(dK[mt][0], dK[mt][1]);
        *reinterpret_cast<float2 *>(&g_updK[o1]) = make_float2(dK[mt][2], dK[mt][3]);
        *reinterpret_cast<float2 *>(&g_updV[o0]) = make_float2(dV[mt][0], dV[mt][1]);
        *reinterpret_cast<float2 *>(&g_updV[o1]) = make_float2(dV[mt][2], dV[mt][3]);
    }
}

// ---------------- final ---------------------------------------------------------------
__global__ __launch_bounds__(256) void final_kernel(
    const float *__restrict__ emK, const float *__restrict__ emV,
    const float *__restrict__ emS, const float *__restrict__ emAge,
    const float *__restrict__ gem, float *__restrict__ out) {
    int bk = blockIdx.x, b = bk >> 3, k = bk & 7;
    int tid = threadIdx.x, warp = tid >> 5, lane = tid & 31;
    float ge = gem[b * NB + k];
    const float invN = 1.f / (float)NN;

    for (int m = warp; m < MM; m += 8) {
        float swv = g_swr[bk * MM + m];
        float denom = fmaxf(swv, 1e-8f);
        float alpha = fminf(ge * swv * invN, 1.f);
        float oma = 1.f - alpha;
        float idn = 1.f / denom;
        size_t off = ((size_t)bk * MM + m) * DD + lane * 4;
        float4 uk = *reinterpret_cast<const float4 *>(&g_updK[off]);
        uk.x *= idn; uk.y *= idn; uk.z *= idn; uk.w *= idn;
        float sq = uk.x * uk.x + uk.y * uk.y + uk.z * uk.z + uk.w * uk.w;
#pragma unroll
        for (int o = 16; o; o >>= 1) sq += __shfl_xor_sync(0xffffffffu, sq, o);
        float inv = 1.f / fmaxf(sqrtf(sq), 1e-12f);
        float ai = alpha * inv;
        float4 ek = *reinterpret_cast<const float4 *>(&emK[off]);
        *reinterpret_cast<float4 *>(&out[OFF_K + off]) =
            make_float4(oma * ek.x + ai * uk.x, oma * ek.y + ai * uk.y,
                        oma * ek.z + ai * uk.z, oma * ek.w + ai * uk.w);
        float4 uv = *reinterpret_cast<const float4 *>(&g_updV[off]);
        uv.x *= idn; uv.y *= idn; uv.z *= idn; uv.w *= idn;
        float4 ev = *reinterpret_cast<const float4 *>(&emV[off]);
        *reinterpret_cast<float4 *>(&out[OFF_V + off]) =
            make_float4(oma * ev.x + alpha * uv.x, oma * ev.y + alpha * uv.y,
                        oma * ev.z + alpha * uv.z, oma * ev.w + alpha * uv.w);
    }

    __shared__ float red[8];
    __shared__ float stot;
    float part = 0.f, sn[2], al[2];
#pragma unroll
    for (int i = 0; i < 2; i++) {
        int m = tid + i * 256;
        float swv = g_swr[bk * MM + m];
        al[i] = fminf(ge * swv * invN, 1.f);
        float v = emS[bk * MM + m] + al[i];
        v = fminf(fmaxf(v, 0.f), 3.0f);
        sn[i] = v; part += v;
    }
#pragma unroll
    for (int o = 16; o; o >>= 1) part += __shfl_xor_sync(0xffffffffu, part, o);
    if (lane == 0) red[warp] = part;
    __syncthreads();
    if (tid == 0) {
        float t = 0.f;
        for (int i = 0; i < 8; i++) t += red[i];
        stot = t;
    }
    __syncthreads();
    float scale = fminf(1.f, 32.0f / fmaxf(stot, 1e-8f));
#pragma unroll
    for (int i = 0; i < 2; i++) {
        int m = tid + i * 256;
        out[OFF_S + bk * MM + m] = sn[i] * scale;
        out[OFF_AGE + bk * MM + m] = emAge[bk * MM + m] * (1.f - al[i]);
    }
}

// ---------------- launcher --------------------------------------------------------------
extern "C" void kernel_launch(void *const *d_in, const int *in_sizes, int n_in,
                              void *d_out, int out_size) {
    const float *seed     = (const float *)d_in[0];
    const float *wcand    = (const float *)d_in[1];
    const float *surprise = (const float *)d_in[2];
    const float *gem      = (const float *)d_in[3];
    const float *emK      = (const float *)d_in[4];
    const float *emV      = (const float *)d_in[5];
    const float *emS      = (const float *)d_in[6];
    const float *emAge    = (const float *)d_in[7];
    const float *w1       = (const float *)d_in[8];
    const float *w2       = (const float *)d_in[9];
    const float *gb       = (const float *)d_in[10];
    const float *rtau     = (const float *)d_in[11];
    const float *rtauw    = (const float *)d_in[12];
    float *out = (float *)d_out;

    cudaFuncSetAttribute(scores_mma_kernel<0>,
                         cudaFuncAttributeMaxDynamicSharedMemorySize, S4_BYTES);
    cudaFuncSetAttribute(scores_mma_kernel<1>,
                         cudaFuncAttributeMaxDynamicSharedMemorySize, S4_BYTES);
    cudaFuncSetAttribute(av_mma_kernel<0>,
                         cudaFuncAttributeMaxDynamicSharedMemorySize, A4_BYTES);
    cudaFuncSetAttribute(av_mma_kernel<1>,
                         cudaFuncAttributeMaxDynamicSharedMemorySize, A4_BYTES);
    cudaFuncSetAttribute(av_mma_kernel<2>,
                         cudaFuncAttributeMaxDynamicSharedMemorySize, A4_BYTES);
    cudaFuncSetAttribute(updkv_mma_kernel,
                         cudaFuncAttributeMaxDynamicSharedMemorySize, U2_BYTES);

    dim3 gS(32, 64), gA(16, 64), gU(8, 64);
    dim3 gT(16, 4, 64), bT(32, 8);
    dim3 gW(32, 4, 8);

    kpack_kernel<<<4096, 256>>>(emK);
    transpose_v_kernel<<<gT, bT>>>(emV);
    init_y_kernel<<<8192, 256>>>(seed);
    wnorm_kernel<<<8192, 128>>>(wcand, surprise);
    wtpack_kernel<<<gW, bT>>>(wcand);

    scores_mma_kernel<0><<<gS, 256, S4_BYTES>>>(emS, rtau, rtauw);
    av_mma_kernel<0><<<gA, 128, A4_BYTES>>>(w1, w2, gb, seed, wcand, out);
    scores_mma_kernel<0><<<gS, 256, S4_BYTES>>>(emS, rtau, rtauw);
    av_mma_kernel<1><<<gA, 128, A4_BYTES>>>(w1, w2, gb, seed, wcand, out);

    scores_mma_kernel<1><<<gS, 256, S4_BYTES>>>(emS, rtau, rtauw);
    av_mma_kernel<2><<<gA, 128, A4_BYTES>>>(w1, w2, gb, seed, wcand, out);

    repack_kernel<<<dim3(4, 64), 256>>>();
    updkv_mma_kernel<<<gU, 256, U2_BYTES>>>();
    final_kernel<<<64, 256>>>(emK, emV, emS, emAge, gem, out);
}